// round 1
// baseline (speedup 1.0000x reference)
#include <cuda_runtime.h>

#define BATCH 8
#define MM 256
#define NN 256
#define CI 64
#define CO 64
#define KK 4
#define MODES 32

// ---------------- scratch (device globals; no allocations) ----------------
__device__ float2 g_wy [BATCH*MODES*CI*CO];   // [b][f][i][o]
__device__ float2 g_wx [BATCH*MODES*CI*CO];
__device__ float2 g_XfY[BATCH*MODES*MM*CI];   // [b][f][m][i]
__device__ float2 g_XfX[BATCH*MODES*NN*CI];   // [b][f][n][i]
__device__ float2 g_YfY[BATCH*MODES*MM*CO];   // [b][f][m][o]
__device__ float2 g_YfX[BATCH*MODES*NN*CO];   // [b][f][n][o]
__device__ float  g_xsum[(size_t)BATCH*MM*NN*CO]; // [b][m][n][o]

// ---------------- K0: per-batch spectral weights ----------------
__global__ void k_weights(const float* __restrict__ att,
                          const float* __restrict__ fwy,
                          const float* __restrict__ fwx) {
    int gid = blockIdx.x * 256 + threadIdx.x;          // b*2^17 + f*2^12 + i*2^6 + o
    int o = gid & 63, i = (gid >> 6) & 63, f = (gid >> 12) & 31, b = gid >> 17;
    float a0 = att[b*KK+0], a1 = att[b*KK+1], a2 = att[b*KK+2], a3 = att[b*KK+3];
    const int ks = CI*CO*MODES*2;
    int base = ((i*CO + o)*MODES + f)*2;
    float yr, yi, xr, xi;
    yr = a0*fwy[base       ] + a1*fwy[base+ks       ] + a2*fwy[base+2*ks  ] + a3*fwy[base+3*ks  ];
    yi = a0*fwy[base+1     ] + a1*fwy[base+ks+1     ] + a2*fwy[base+2*ks+1] + a3*fwy[base+3*ks+1];
    xr = a0*fwx[base       ] + a1*fwx[base+ks       ] + a2*fwx[base+2*ks  ] + a3*fwx[base+3*ks  ];
    xi = a0*fwx[base+1     ] + a1*fwx[base+ks+1     ] + a2*fwx[base+2*ks+1] + a3*fwx[base+3*ks+1];
    g_wy[gid] = make_float2(yr, yi);
    g_wx[gid] = make_float2(xr, xi);
}

// ---------------- K1Y: forward 32-mode DFT along N ----------------
__global__ void __launch_bounds__(256) k_fwdY(const float* __restrict__ x) {
    extern __shared__ float smf[];
    float* sx = smf;            // [n][i]  16384
    float* ct = smf + 16384;    // 256
    float* st = ct + 256;       // 256
    int t = threadIdx.x;
    int b = blockIdx.x >> 8, m = blockIdx.x & 255;
    const float4* xr4 = (const float4*)(x + ((size_t)(b*MM + m))*NN*CI);
    float4* sx4 = (float4*)sx;
    #pragma unroll
    for (int it = 0; it < 16; it++) sx4[it*256 + t] = xr4[it*256 + t];
    ct[t] = cospif(t * (1.0f/128.0f));
    st[t] = sinpif(t * (1.0f/128.0f));
    __syncthreads();

    int f = t >> 3, ib = (t & 7) * 8;
    float re[8], im[8];
    #pragma unroll
    for (int r = 0; r < 8; r++) { re[r] = 0.f; im[r] = 0.f; }
    int idx = 0;
    for (int n = 0; n < NN; n++) {
        float c = ct[idx], s = st[idx];
        idx = (idx + f) & 255;
        const float4* sv = (const float4*)(sx + n*CI + ib);
        float4 v0 = sv[0], v1 = sv[1];
        float v[8] = {v0.x, v0.y, v0.z, v0.w, v1.x, v1.y, v1.z, v1.w};
        #pragma unroll
        for (int r = 0; r < 8; r++) {
            re[r] = fmaf(v[r],  c, re[r]);
            im[r] = fmaf(v[r], -s, im[r]);
        }
    }
    const float sc = 0.0625f;   // 1/sqrt(256)
    float4* out4 = (float4*)(g_XfY + ((size_t)(b*MODES + f)*MM + m)*CI + ib);
    #pragma unroll
    for (int r = 0; r < 4; r++)
        out4[r] = make_float4(re[2*r]*sc, im[2*r]*sc, re[2*r+1]*sc, im[2*r+1]*sc);
}

// ---------------- K1X: forward 32-mode sine transform along M (odd ext. 510) ----------------
__global__ void __launch_bounds__(256) k_fwdX(const float* __restrict__ x) {
    extern __shared__ float smf[];
    float* sx  = smf;           // [m][i] 16384
    float* st5 = smf + 16384;   // 510
    int t = threadIdx.x;
    int b = blockIdx.x >> 8, n = blockIdx.x & 255;
    {
        int i4 = (t & 15) * 4;
        int mb = t >> 4;
        #pragma unroll
        for (int j = 0; j < 16; j++) {
            int m = j*16 + mb;
            *(float4*)(sx + m*CI + i4) =
                *(const float4*)(x + (((size_t)(b*MM + m))*NN + n)*CI + i4);
        }
    }
    st5[t] = sinpif(t * (1.0f/255.0f));
    if (t + 256 < 510) st5[t+256] = sinpif((t+256) * (1.0f/255.0f));
    __syncthreads();

    int f = t >> 3, ib = (t & 7) * 8;
    float im[8];
    #pragma unroll
    for (int r = 0; r < 8; r++) im[r] = 0.f;
    int idx = f;                     // (f*m) mod 510 at m=1
    for (int m = 1; m <= 254; m++) {
        float s = st5[idx];
        idx += f; if (idx >= 510) idx -= 510;
        const float4* sv = (const float4*)(sx + m*CI + ib);
        float4 v0 = sv[0], v1 = sv[1];
        float v[8] = {v0.x, v0.y, v0.z, v0.w, v1.x, v1.y, v1.z, v1.w};
        #pragma unroll
        for (int r = 0; r < 8; r++) im[r] = fmaf(v[r], -s, im[r]);
    }
    const float inv = 0.04428074428f;  // 1/sqrt(510)
    float sgn = (f & 1) ? -1.f : 1.f;
    float re[8], iv[8];
    #pragma unroll
    for (int r = 0; r < 8; r++) {
        re[r] = (sx[0*CI + ib + r] + sgn * sx[255*CI + ib + r]) * inv;
        iv[r] = 2.f * inv * im[r];     // = -2*inv*sum(x*sin)
    }
    float4* out4 = (float4*)(g_XfX + ((size_t)(b*MODES + f)*NN + n)*CI + ib);
    #pragma unroll
    for (int r = 0; r < 4; r++)
        out4[r] = make_float4(re[2*r], iv[2*r], re[2*r+1], iv[2*r+1]);
}

// ---------------- K2: per-(branch,b,f) complex GEMM 256x64 @ 64x64 ----------------
__global__ void __launch_bounds__(256) k_mix() {
    extern __shared__ float smf[];
    float2* Ws = (float2*)smf;          // [i][o] 4096
    float2* As = Ws + 4096;             // [256][17] padded
    int t = threadIdx.x;
    int z = blockIdx.x;
    int branch = z >> 8;
    int bf = z & 255;
    const float2* A = (branch ? g_XfX : g_XfY) + (size_t)bf*MM*CI;
    const float2* W = (branch ? g_wx  : g_wy ) + (size_t)bf*CI*CO;
    float2*       C = (branch ? g_YfX : g_YfY) + (size_t)bf*MM*CO;

    #pragma unroll
    for (int it = 0; it < 16; it++) Ws[it*256 + t] = W[it*256 + t];

    float2 acc[8][8];
    #pragma unroll
    for (int r = 0; r < 8; r++)
        #pragma unroll
        for (int c = 0; c < 8; c++) acc[r][c] = make_float2(0.f, 0.f);

    int m0 = (t >> 3) * 8, o0 = (t & 7) * 8;
    for (int kc = 0; kc < 4; kc++) {
        __syncthreads();
        #pragma unroll
        for (int it = 0; it < 16; it++) {
            int flat = it*256 + t;
            int row = flat >> 4, col = flat & 15;
            As[row*17 + col] = A[row*64 + kc*16 + col];
        }
        __syncthreads();
        #pragma unroll
        for (int ii = 0; ii < 16; ii++) {
            int i = kc*16 + ii;
            float2 a[8], w[8];
            #pragma unroll
            for (int r = 0; r < 8; r++) a[r] = As[(m0 + r)*17 + ii];
            #pragma unroll
            for (int c = 0; c < 8; c++) w[c] = Ws[i*64 + o0 + c];
            #pragma unroll
            for (int r = 0; r < 8; r++)
                #pragma unroll
                for (int c = 0; c < 8; c++) {
                    acc[r][c].x = fmaf(a[r].x, w[c].x, fmaf(-a[r].y, w[c].y, acc[r][c].x));
                    acc[r][c].y = fmaf(a[r].x, w[c].y, fmaf( a[r].y, w[c].x, acc[r][c].y));
                }
        }
    }
    #pragma unroll
    for (int r = 0; r < 8; r++)
        #pragma unroll
        for (int c = 0; c < 8; c++)
            C[(size_t)(m0 + r)*CO + o0 + c] = acc[r][c];
}

// ---------------- K3Y: inverse synthesis along N, writes g_xsum ----------------
__global__ void __launch_bounds__(256) k_invY() {
    extern __shared__ float smf[];
    float* cre = smf;            // [f][o] 2048
    float* cim = smf + 2048;
    float* ct  = smf + 4096;     // 256
    float* st  = ct + 256;
    int t = threadIdx.x;
    int b = blockIdx.x >> 8, m = blockIdx.x & 255;
    const float2* Y = g_YfY + ((size_t)b*MODES*MM + m)*CO;
    #pragma unroll
    for (int it = 0; it < 8; it++) {
        int flat = it*256 + t;
        int f = flat >> 6;
        float2 v = Y[(size_t)f*MM*CO + (flat & 63)];
        cre[flat] = v.x * ((f == 0) ? 0.0625f : 0.125f);  // (1 or 2)/sqrt(256)
        cim[flat] = v.y * 0.125f;                          // f=0 killed by st[0]=0
    }
    ct[t] = cospif(t * (1.0f/128.0f));
    st[t] = sinpif(t * (1.0f/128.0f));
    __syncthreads();

    int n = t;
    float4 acc[16];
    #pragma unroll
    for (int q = 0; q < 16; q++) acc[q] = make_float4(0.f,0.f,0.f,0.f);
    int idx = 0;
    for (int f = 0; f < MODES; f++) {
        float c = ct[idx], s = st[idx];
        idx = (idx + n) & 255;
        const float4* r4 = (const float4*)(cre + f*64);
        const float4* i4 = (const float4*)(cim + f*64);
        #pragma unroll
        for (int q = 0; q < 16; q++) {
            float4 rv = r4[q], iv = i4[q];
            acc[q].x = fmaf(rv.x, c, fmaf(iv.x, -s, acc[q].x));
            acc[q].y = fmaf(rv.y, c, fmaf(iv.y, -s, acc[q].y));
            acc[q].z = fmaf(rv.z, c, fmaf(iv.z, -s, acc[q].z));
            acc[q].w = fmaf(rv.w, c, fmaf(iv.w, -s, acc[q].w));
        }
    }
    float4* out = (float4*)(g_xsum + (((size_t)(b*MM + m))*NN + n)*CO);
    #pragma unroll
    for (int q = 0; q < 16; q++) out[q] = acc[q];
}

// ---------------- K3X: inverse synthesis along M, adds into g_xsum ----------------
__global__ void __launch_bounds__(256) k_invX() {
    extern __shared__ float smf[];
    float* cre = smf;            // 2048
    float* cim = smf + 2048;
    float* ct5 = smf + 4096;     // 510
    float* st5 = ct5 + 510;      // 510
    int t = threadIdx.x;
    int b = blockIdx.x >> 8, n = blockIdx.x & 255;
    const float inv = 0.04428074428f;  // 1/sqrt(510)
    const float2* Y = g_YfX + ((size_t)b*MODES*NN + n)*CO;
    #pragma unroll
    for (int it = 0; it < 8; it++) {
        int flat = it*256 + t;
        int f = flat >> 6;
        float2 v = Y[(size_t)f*NN*CO + (flat & 63)];
        cre[flat] = v.x * (((f == 0) ? 1.f : 2.f) * inv);
        cim[flat] = v.y * (2.f * inv);
    }
    ct5[t] = cospif(t * (1.0f/255.0f));
    st5[t] = sinpif(t * (1.0f/255.0f));
    if (t + 256 < 510) {
        ct5[t+256] = cospif((t+256) * (1.0f/255.0f));
        st5[t+256] = sinpif((t+256) * (1.0f/255.0f));
    }
    __syncthreads();

    int m = t;
    float4 acc[16];
    #pragma unroll
    for (int q = 0; q < 16; q++) acc[q] = make_float4(0.f,0.f,0.f,0.f);
    int idx = 0;
    for (int f = 0; f < MODES; f++) {
        float c = ct5[idx], s = st5[idx];
        idx += m; if (idx >= 510) idx -= 510;
        const float4* r4 = (const float4*)(cre + f*64);
        const float4* i4 = (const float4*)(cim + f*64);
        #pragma unroll
        for (int q = 0; q < 16; q++) {
            float4 rv = r4[q], iv = i4[q];
            acc[q].x = fmaf(rv.x, c, fmaf(iv.x, -s, acc[q].x));
            acc[q].y = fmaf(rv.y, c, fmaf(iv.y, -s, acc[q].y));
            acc[q].z = fmaf(rv.z, c, fmaf(iv.z, -s, acc[q].z));
            acc[q].w = fmaf(rv.w, c, fmaf(iv.w, -s, acc[q].w));
        }
    }
    float4* out = (float4*)(g_xsum + (((size_t)(b*MM + m))*NN + n)*CO);
    #pragma unroll
    for (int q = 0; q < 16; q++) {
        float4 v = out[q];
        v.x += acc[q].x; v.y += acc[q].y; v.z += acc[q].z; v.w += acc[q].w;
        out[q] = v;
    }
}

// ---------------- K4: fused MLP (64->256 relu ->64) + LayerNorm ----------------
__global__ void __launch_bounds__(256) k_mlp(const float* __restrict__ w1,
                                             const float* __restrict__ b1,
                                             const float* __restrict__ w2,
                                             const float* __restrict__ b2,
                                             const float* __restrict__ gamma,
                                             const float* __restrict__ beta,
                                             float* __restrict__ out) {
    extern __shared__ float smf[];
    float* w1T = smf;             // [j][i] 16384
    float* w2s = smf + 16384;     // [j][o] 16384
    float* b1s = smf + 32768;     // 256
    float* b2s = b1s + 256;       // 64
    float* gs  = b2s + 64;        // 64
    float* bs  = gs + 64;         // 64
    int t = threadIdx.x;
    #pragma unroll 4
    for (int it = 0; it < 64; it++) {
        int flat = it*256 + t;
        w1T[(flat & 255)*64 + (flat >> 8)] = w1[flat];   // w1 is [i=64][j=256]
        w2s[flat] = w2[flat];                             // w2 is [j=256][o=64]
    }
    b1s[t] = b1[t];
    if (t < 64) { b2s[t] = b2[t]; gs[t] = gamma[t]; bs[t] = beta[t]; }
    __syncthreads();

    size_t p = (size_t)blockIdx.x * 256 + t;
    float4 s4[16], o4[16];
    const float4* sp = (const float4*)(g_xsum + p*CO);
    #pragma unroll
    for (int q = 0; q < 16; q++) s4[q] = sp[q];
    const float4* b24 = (const float4*)b2s;
    #pragma unroll
    for (int q = 0; q < 16; q++) o4[q] = b24[q];

    for (int j = 0; j < 256; j++) {
        const float4* w1r = (const float4*)(w1T + j*64);
        float h0 = 0.f, h1 = 0.f, h2 = 0.f, h3 = 0.f;
        #pragma unroll
        for (int q = 0; q < 16; q++) {
            float4 wv = w1r[q];
            h0 = fmaf(s4[q].x, wv.x, h0);
            h1 = fmaf(s4[q].y, wv.y, h1);
            h2 = fmaf(s4[q].z, wv.z, h2);
            h3 = fmaf(s4[q].w, wv.w, h3);
        }
        float h = fmaxf((h0 + h1) + (h2 + h3) + b1s[j], 0.f);
        const float4* w2r = (const float4*)(w2s + j*64);
        #pragma unroll
        for (int q = 0; q < 16; q++) {
            float4 wv = w2r[q];
            o4[q].x = fmaf(h, wv.x, o4[q].x);
            o4[q].y = fmaf(h, wv.y, o4[q].y);
            o4[q].z = fmaf(h, wv.z, o4[q].z);
            o4[q].w = fmaf(h, wv.w, o4[q].w);
        }
    }
    // LayerNorm over O=64
    float mu = 0.f;
    #pragma unroll
    for (int q = 0; q < 16; q++) mu += o4[q].x + o4[q].y + o4[q].z + o4[q].w;
    mu *= (1.f/64.f);
    float var = 0.f;
    #pragma unroll
    for (int q = 0; q < 16; q++) {
        float dx = o4[q].x - mu, dy = o4[q].y - mu, dz = o4[q].z - mu, dw = o4[q].w - mu;
        var += dx*dx + dy*dy + dz*dz + dw*dw;
    }
    var *= (1.f/64.f);
    float rinv = rsqrtf(var + 1e-5f);
    const float4* g4 = (const float4*)gs;
    const float4* be4 = (const float4*)bs;
    float4* op = (float4*)(out + p*CO);
    #pragma unroll
    for (int q = 0; q < 16; q++) {
        float4 gv = g4[q], bv = be4[q], r;
        r.x = (o4[q].x - mu) * rinv * gv.x + bv.x;
        r.y = (o4[q].y - mu) * rinv * gv.y + bv.y;
        r.z = (o4[q].z - mu) * rinv * gv.z + bv.z;
        r.w = (o4[q].w - mu) * rinv * gv.w + bv.w;
        op[q] = r;
    }
}

// ---------------- launcher ----------------
extern "C" void kernel_launch(void* const* d_in, const int* in_sizes, int n_in,
                              void* d_out, int out_size) {
    (void)in_sizes; (void)n_in; (void)out_size;
    const float* x     = (const float*)d_in[0];
    const float* att   = (const float*)d_in[1];
    const float* fwy   = (const float*)d_in[2];
    const float* fwx   = (const float*)d_in[3];
    const float* w1    = (const float*)d_in[4];
    const float* b1    = (const float*)d_in[5];
    const float* w2    = (const float*)d_in[6];
    const float* b2    = (const float*)d_in[7];
    const float* gamma = (const float*)d_in[8];
    const float* beta  = (const float*)d_in[9];
    float* out = (float*)d_out;

    const int SM_FWDY = (16384 + 512) * 4;
    const int SM_FWDX = (16384 + 512) * 4;
    const int SM_MIX  = (4096 + 256*17) * 8;
    const int SM_INVY = (4096 + 512) * 4;
    const int SM_INVX = (4096 + 1020) * 4;
    const int SM_MLP  = (32768 + 256 + 64*3) * 4;

    cudaFuncSetAttribute(k_fwdY, cudaFuncAttributeMaxDynamicSharedMemorySize, SM_FWDY);
    cudaFuncSetAttribute(k_fwdX, cudaFuncAttributeMaxDynamicSharedMemorySize, SM_FWDX);
    cudaFuncSetAttribute(k_mix,  cudaFuncAttributeMaxDynamicSharedMemorySize, SM_MIX);
    cudaFuncSetAttribute(k_mlp,  cudaFuncAttributeMaxDynamicSharedMemorySize, SM_MLP);

    k_weights<<<(BATCH*MODES*CI*CO)/256, 256>>>(att, fwy, fwx);
    k_fwdY<<<BATCH*MM, 256, SM_FWDY>>>(x);
    k_fwdX<<<BATCH*NN, 256, SM_FWDX>>>(x);
    k_mix <<<2*BATCH*MODES, 256, SM_MIX>>>();
    k_invY<<<BATCH*MM, 256, SM_INVY>>>();
    k_invX<<<BATCH*NN, 256, SM_INVX>>>();
    k_mlp <<<(BATCH*MM*NN)/256, 256, SM_MLP>>>(w1, b1, w2, b2, gamma, beta, out);
}

// round 2
// speedup vs baseline: 1.0290x; 1.0290x over previous
#include <cuda_runtime.h>

#define BATCH 8
#define MM 256
#define NN 256
#define CI 64
#define CO 64
#define KK 4
#define MODES 32

typedef unsigned long long u64;

__device__ __forceinline__ u64 pk2(float lo, float hi) {
    u64 r; asm("mov.b64 %0,{%1,%2};" : "=l"(r) : "f"(lo), "f"(hi)); return r;
}
__device__ __forceinline__ void upk2(u64 v, float& a, float& b) {
    asm("mov.b64 {%0,%1},%2;" : "=f"(a), "=f"(b) : "l"(v));
}
__device__ __forceinline__ u64 ffma2(u64 a, u64 b, u64 c) {
    u64 d; asm("fma.rn.f32x2 %0,%1,%2,%3;" : "=l"(d) : "l"(a), "l"(b), "l"(c)); return d;
}
__device__ __forceinline__ u64 fmul2(u64 a, u64 b) {
    u64 d; asm("mul.rn.f32x2 %0,%1,%2;" : "=l"(d) : "l"(a), "l"(b)); return d;
}
__device__ __forceinline__ u64 fadd2(u64 a, u64 b) {
    u64 d; asm("add.rn.f32x2 %0,%1,%2;" : "=l"(d) : "l"(a), "l"(b)); return d;
}

// ---------------- scratch ----------------
__device__ float2 g_wy [BATCH*MODES*CI*CO];
__device__ float2 g_wx [BATCH*MODES*CI*CO];
__device__ float2 g_XfY[BATCH*MODES*MM*CI];
__device__ float2 g_XfX[BATCH*MODES*NN*CI];
__device__ float2 g_YfY[BATCH*MODES*MM*CO];
__device__ float2 g_YfX[BATCH*MODES*NN*CO];
__device__ float  g_xsum[(size_t)BATCH*MM*NN*CO];

// ---------------- K0: spectral weights ----------------
__global__ void k_weights(const float* __restrict__ att,
                          const float* __restrict__ fwy,
                          const float* __restrict__ fwx) {
    int gid = blockIdx.x * 256 + threadIdx.x;
    int o = gid & 63, i = (gid >> 6) & 63, f = (gid >> 12) & 31, b = gid >> 17;
    float a0 = att[b*KK+0], a1 = att[b*KK+1], a2 = att[b*KK+2], a3 = att[b*KK+3];
    const int ks = CI*CO*MODES*2;
    int base = ((i*CO + o)*MODES + f)*2;
    float yr, yi, xr, xi;
    yr = a0*fwy[base   ] + a1*fwy[base+ks   ] + a2*fwy[base+2*ks  ] + a3*fwy[base+3*ks  ];
    yi = a0*fwy[base+1 ] + a1*fwy[base+ks+1 ] + a2*fwy[base+2*ks+1] + a3*fwy[base+3*ks+1];
    xr = a0*fwx[base   ] + a1*fwx[base+ks   ] + a2*fwx[base+2*ks  ] + a3*fwx[base+3*ks  ];
    xi = a0*fwx[base+1 ] + a1*fwx[base+ks+1 ] + a2*fwx[base+2*ks+1] + a3*fwx[base+3*ks+1];
    g_wy[gid] = make_float2(yr, yi);
    g_wx[gid] = make_float2(xr, xi);
}

// ---------------- K1Y: forward 32-mode DFT along N (packed f32x2) ----------------
__global__ void __launch_bounds__(256) k_fwdY(const float* __restrict__ x) {
    extern __shared__ float smf[];
    float* sx = smf;                       // [n][i] 16384 floats
    u64* ct2 = (u64*)(smf + 16384);        // 256 packed (c,c)
    u64* st2 = ct2 + 256;                  // 256 packed (-s,-s)
    int t = threadIdx.x;
    int b = blockIdx.x >> 8, m = blockIdx.x & 255;
    const float4* xr4 = (const float4*)(x + ((size_t)(b*MM + m))*NN*CI);
    float4* sx4 = (float4*)sx;
    #pragma unroll
    for (int it = 0; it < 16; it++) sx4[it*256 + t] = xr4[it*256 + t];
    {
        float c = cospif(t * (1.0f/128.0f));
        float s = sinpif(t * (1.0f/128.0f));
        ct2[t] = pk2(c, c);
        st2[t] = pk2(-s, -s);
    }
    __syncthreads();

    int f = t >> 3, ib = (t & 7) * 8;
    u64 re2[4] = {0,0,0,0}, im2[4] = {0,0,0,0};
    int idx = 0;
    for (int n = 0; n < NN; n++) {
        u64 cc = ct2[idx], ss = st2[idx];
        idx = (idx + f) & 255;
        const ulonglong2* sv = (const ulonglong2*)(sx + n*CI + ib);
        ulonglong2 p0 = sv[0], p1 = sv[1];
        re2[0] = ffma2(p0.x, cc, re2[0]);  im2[0] = ffma2(p0.x, ss, im2[0]);
        re2[1] = ffma2(p0.y, cc, re2[1]);  im2[1] = ffma2(p0.y, ss, im2[1]);
        re2[2] = ffma2(p1.x, cc, re2[2]);  im2[2] = ffma2(p1.x, ss, im2[2]);
        re2[3] = ffma2(p1.y, cc, re2[3]);  im2[3] = ffma2(p1.y, ss, im2[3]);
    }
    const u64 sc2 = pk2(0.0625f, 0.0625f);
    float4* out4 = (float4*)(g_XfY + ((size_t)(b*MODES + f)*MM + m)*CI + ib);
    #pragma unroll
    for (int q = 0; q < 4; q++) {
        float ra, rb, ia, ib2;
        upk2(fmul2(re2[q], sc2), ra, rb);
        upk2(fmul2(im2[q], sc2), ia, ib2);
        out4[q] = make_float4(ra, ia, rb, ib2);
    }
}

// ---------------- K1X: forward sine transform along M (packed) ----------------
__global__ void __launch_bounds__(256) k_fwdX(const float* __restrict__ x) {
    extern __shared__ float smf[];
    float* sx  = smf;                      // [m][i] 16384 floats
    u64* st5 = (u64*)(smf + 16384);        // 510 packed (-s,-s)
    int t = threadIdx.x;
    int b = blockIdx.x >> 8, n = blockIdx.x & 255;
    {
        int i4 = (t & 15) * 4;
        int mb = t >> 4;
        #pragma unroll
        for (int j = 0; j < 16; j++) {
            int m = j*16 + mb;
            *(float4*)(sx + m*CI + i4) =
                *(const float4*)(x + (((size_t)(b*MM + m))*NN + n)*CI + i4);
        }
    }
    {
        float s = sinpif(t * (1.0f/255.0f));
        st5[t] = pk2(-s, -s);
        if (t + 256 < 510) {
            float s2 = sinpif((t+256) * (1.0f/255.0f));
            st5[t+256] = pk2(-s2, -s2);
        }
    }
    __syncthreads();

    int f = t >> 3, ib = (t & 7) * 8;
    u64 im2[4] = {0,0,0,0};
    int idx = f;
    for (int m = 1; m <= 254; m++) {
        u64 ss = st5[idx];
        idx += f; if (idx >= 510) idx -= 510;
        const ulonglong2* sv = (const ulonglong2*)(sx + m*CI + ib);
        ulonglong2 p0 = sv[0], p1 = sv[1];
        im2[0] = ffma2(p0.x, ss, im2[0]);
        im2[1] = ffma2(p0.y, ss, im2[1]);
        im2[2] = ffma2(p1.x, ss, im2[2]);
        im2[3] = ffma2(p1.y, ss, im2[3]);
    }
    const float inv = 0.04428074428f;   // 1/sqrt(510)
    float sgn = (f & 1) ? -1.f : 1.f;
    float4* out4 = (float4*)(g_XfX + ((size_t)(b*MODES + f)*NN + n)*CI + ib);
    #pragma unroll
    for (int q = 0; q < 4; q++) {
        float ia, ib2;
        upk2(im2[q], ia, ib2);
        int r0 = 2*q, r1 = 2*q + 1;
        float reA = (sx[ib + r0] + sgn * sx[255*CI + ib + r0]) * inv;
        float reB = (sx[ib + r1] + sgn * sx[255*CI + ib + r1]) * inv;
        out4[q] = make_float4(reA, 2.f*inv*ia, reB, 2.f*inv*ib2);
    }
}

// ---------------- K2: complex GEMM (packed f32x2 complex MAC) ----------------
__global__ void __launch_bounds__(256) k_mix() {
    extern __shared__ float smf[];
    u64* Ws1 = (u64*)smf;             // [i][o] (wx, wy)     4096 u64
    u64* Ws2 = Ws1 + 4096;            // [i][o] (-wy, wx)    4096 u64
    u64* As  = Ws2 + 4096;            // [256][17] (ax, ay)
    int t = threadIdx.x;
    int z = blockIdx.x;
    int branch = z >> 8;
    int bf = z & 255;
    const float2* A = (branch ? g_XfX : g_XfY) + (size_t)bf*MM*CI;
    const float2* W = (branch ? g_wx  : g_wy ) + (size_t)bf*CI*CO;
    float2*       C = (branch ? g_YfX : g_YfY) + (size_t)bf*MM*CO;

    #pragma unroll
    for (int it = 0; it < 16; it++) {
        float2 w = W[it*256 + t];
        Ws1[it*256 + t] = pk2(w.x, w.y);
        Ws2[it*256 + t] = pk2(-w.y, w.x);
    }

    u64 acc[8][8];
    #pragma unroll
    for (int r = 0; r < 8; r++)
        #pragma unroll
        for (int c = 0; c < 8; c++) acc[r][c] = 0;

    int m0 = (t >> 3) * 8, o0 = (t & 7) * 8;
    for (int kc = 0; kc < 4; kc++) {
        __syncthreads();
        #pragma unroll
        for (int it = 0; it < 16; it++) {
            int flat = it*256 + t;
            int row = flat >> 4, col = flat & 15;
            float2 a = A[row*64 + kc*16 + col];
            As[row*17 + col] = pk2(a.x, a.y);
        }
        __syncthreads();
        #pragma unroll
        for (int ii = 0; ii < 16; ii++) {
            int i = kc*16 + ii;
            u64 axx[8], ayy[8], w1p[8], w2p[8];
            #pragma unroll
            for (int r = 0; r < 8; r++) {
                float ax, ay;
                upk2(As[(m0 + r)*17 + ii], ax, ay);
                axx[r] = pk2(ax, ax);
                ayy[r] = pk2(ay, ay);
            }
            #pragma unroll
            for (int c = 0; c < 8; c++) {
                w1p[c] = Ws1[i*64 + o0 + c];
                w2p[c] = Ws2[i*64 + o0 + c];
            }
            #pragma unroll
            for (int r = 0; r < 8; r++)
                #pragma unroll
                for (int c = 0; c < 8; c++)
                    acc[r][c] = ffma2(axx[r], w1p[c], ffma2(ayy[r], w2p[c], acc[r][c]));
        }
    }
    u64* Cu = (u64*)C;
    #pragma unroll
    for (int r = 0; r < 8; r++)
        #pragma unroll
        for (int c = 0; c < 8; c++)
            Cu[(size_t)(m0 + r)*CO + o0 + c] = acc[r][c];
}

// ---------------- K3Y: inverse synthesis along N (packed) ----------------
__global__ void __launch_bounds__(256) k_invY() {
    extern __shared__ float smf[];
    float* cre = smf;            // [f][o] 2048
    float* cim = smf + 2048;
    float* ct  = smf + 4096;     // 256
    float* st  = ct + 256;
    int t = threadIdx.x;
    int b = blockIdx.x >> 8, m = blockIdx.x & 255;
    const float2* Y = g_YfY + ((size_t)b*MODES*MM + m)*CO;
    #pragma unroll
    for (int it = 0; it < 8; it++) {
        int flat = it*256 + t;
        int f = flat >> 6;
        float2 v = Y[(size_t)f*MM*CO + (flat & 63)];
        cre[flat] = v.x * ((f == 0) ? 0.0625f : 0.125f);
        cim[flat] = v.y * 0.125f;
    }
    ct[t] = cospif(t * (1.0f/128.0f));
    st[t] = sinpif(t * (1.0f/128.0f));
    __syncthreads();

    int n = t;
    u64 acc[32];
    #pragma unroll
    for (int q = 0; q < 32; q++) acc[q] = 0;
    int idx = 0;
    for (int f = 0; f < MODES; f++) {
        float c = ct[idx], s = st[idx];
        idx = (idx + n) & 255;
        u64 cc = pk2(c, c), ss = pk2(-s, -s);
        const ulonglong2* r2 = (const ulonglong2*)(cre + f*64);
        const ulonglong2* i2 = (const ulonglong2*)(cim + f*64);
        #pragma unroll
        for (int q = 0; q < 16; q++) {
            ulonglong2 rp = r2[q], ip = i2[q];
            acc[2*q  ] = ffma2(rp.x, cc, ffma2(ip.x, ss, acc[2*q  ]));
            acc[2*q+1] = ffma2(rp.y, cc, ffma2(ip.y, ss, acc[2*q+1]));
        }
    }
    ulonglong2* out = (ulonglong2*)(g_xsum + (((size_t)(b*MM + m))*NN + n)*CO);
    #pragma unroll
    for (int q = 0; q < 16; q++) {
        ulonglong2 v; v.x = acc[2*q]; v.y = acc[2*q+1];
        out[q] = v;
    }
}

// ---------------- K3X: inverse synthesis along M, accumulate (packed) ----------------
__global__ void __launch_bounds__(256) k_invX() {
    extern __shared__ float smf[];
    float* cre = smf;            // 2048
    float* cim = smf + 2048;
    float* ct5 = smf + 4096;     // 510
    float* st5 = ct5 + 510;
    int t = threadIdx.x;
    int b = blockIdx.x >> 8, n = blockIdx.x & 255;
    const float inv = 0.04428074428f;
    const float2* Y = g_YfX + ((size_t)b*MODES*NN + n)*CO;
    #pragma unroll
    for (int it = 0; it < 8; it++) {
        int flat = it*256 + t;
        int f = flat >> 6;
        float2 v = Y[(size_t)f*NN*CO + (flat & 63)];
        cre[flat] = v.x * (((f == 0) ? 1.f : 2.f) * inv);
        cim[flat] = v.y * (2.f * inv);
    }
    ct5[t] = cospif(t * (1.0f/255.0f));
    st5[t] = sinpif(t * (1.0f/255.0f));
    if (t + 256 < 510) {
        ct5[t+256] = cospif((t+256) * (1.0f/255.0f));
        st5[t+256] = sinpif((t+256) * (1.0f/255.0f));
    }
    __syncthreads();

    int m = t;
    u64 acc[32];
    #pragma unroll
    for (int q = 0; q < 32; q++) acc[q] = 0;
    int idx = 0;
    for (int f = 0; f < MODES; f++) {
        float c = ct5[idx], s = st5[idx];
        idx += m; if (idx >= 510) idx -= 510;
        u64 cc = pk2(c, c), ss = pk2(-s, -s);
        const ulonglong2* r2 = (const ulonglong2*)(cre + f*64);
        const ulonglong2* i2 = (const ulonglong2*)(cim + f*64);
        #pragma unroll
        for (int q = 0; q < 16; q++) {
            ulonglong2 rp = r2[q], ip = i2[q];
            acc[2*q  ] = ffma2(rp.x, cc, ffma2(ip.x, ss, acc[2*q  ]));
            acc[2*q+1] = ffma2(rp.y, cc, ffma2(ip.y, ss, acc[2*q+1]));
        }
    }
    ulonglong2* out = (ulonglong2*)(g_xsum + (((size_t)(b*MM + m))*NN + n)*CO);
    #pragma unroll
    for (int q = 0; q < 16; q++) {
        ulonglong2 v = out[q];
        v.x = fadd2(v.x, acc[2*q]);
        v.y = fadd2(v.y, acc[2*q+1]);
        out[q] = v;
    }
}

// ---------------- K4: fused MLP + LayerNorm (packed) ----------------
__global__ void __launch_bounds__(256) k_mlp(const float* __restrict__ w1,
                                             const float* __restrict__ b1,
                                             const float* __restrict__ w2,
                                             const float* __restrict__ b2,
                                             const float* __restrict__ gamma,
                                             const float* __restrict__ beta,
                                             float* __restrict__ out) {
    extern __shared__ float smf[];
    float* w1T = smf;             // [j][i] 16384
    float* w2s = smf + 16384;     // [j][o] 16384
    float* b1s = smf + 32768;     // 256
    float* b2s = b1s + 256;       // 64
    float* gs  = b2s + 64;
    float* bs  = gs + 64;
    int t = threadIdx.x;
    #pragma unroll 4
    for (int it = 0; it < 64; it++) {
        int flat = it*256 + t;
        w1T[(flat & 255)*64 + (flat >> 8)] = w1[flat];
        w2s[flat] = w2[flat];
    }
    b1s[t] = b1[t];
    if (t < 64) { b2s[t] = b2[t]; gs[t] = gamma[t]; bs[t] = beta[t]; }
    __syncthreads();

    size_t p = (size_t)blockIdx.x * 256 + t;
    ulonglong2 su[16];
    const ulonglong2* sp = (const ulonglong2*)(g_xsum + p*CO);
    #pragma unroll
    for (int q = 0; q < 16; q++) su[q] = sp[q];
    u64 o2[32];
    const ulonglong2* b24 = (const ulonglong2*)b2s;
    #pragma unroll
    for (int q = 0; q < 16; q++) { ulonglong2 bv = b24[q]; o2[2*q] = bv.x; o2[2*q+1] = bv.y; }

    for (int j = 0; j < 256; j++) {
        const ulonglong2* w1r = (const ulonglong2*)(w1T + j*64);
        u64 h2a = 0, h2b = 0;
        #pragma unroll
        for (int q = 0; q < 16; q++) {
            ulonglong2 wp = w1r[q];
            h2a = ffma2(su[q].x, wp.x, h2a);
            h2b = ffma2(su[q].y, wp.y, h2b);
        }
        float a0, a1, c0, c1;
        upk2(h2a, a0, a1); upk2(h2b, c0, c1);
        float h = fmaxf((a0 + a1) + (c0 + c1) + b1s[j], 0.f);
        u64 hh = pk2(h, h);
        const ulonglong2* w2r = (const ulonglong2*)(w2s + j*64);
        #pragma unroll
        for (int q = 0; q < 16; q++) {
            ulonglong2 wp = w2r[q];
            o2[2*q  ] = ffma2(hh, wp.x, o2[2*q  ]);
            o2[2*q+1] = ffma2(hh, wp.y, o2[2*q+1]);
        }
    }
    float ov[64];
    #pragma unroll
    for (int q = 0; q < 32; q++) upk2(o2[q], ov[2*q], ov[2*q+1]);
    float mu = 0.f;
    #pragma unroll
    for (int k = 0; k < 64; k++) mu += ov[k];
    mu *= (1.f/64.f);
    float var = 0.f;
    #pragma unroll
    for (int k = 0; k < 64; k++) { float d = ov[k] - mu; var = fmaf(d, d, var); }
    var *= (1.f/64.f);
    float rinv = rsqrtf(var + 1e-5f);
    float4* op = (float4*)(out + p*CO);
    #pragma unroll
    for (int q = 0; q < 16; q++) {
        float4 r;
        r.x = (ov[4*q  ] - mu) * rinv * gs[4*q  ] + bs[4*q  ];
        r.y = (ov[4*q+1] - mu) * rinv * gs[4*q+1] + bs[4*q+1];
        r.z = (ov[4*q+2] - mu) * rinv * gs[4*q+2] + bs[4*q+2];
        r.w = (ov[4*q+3] - mu) * rinv * gs[4*q+3] + bs[4*q+3];
        op[q] = r;
    }
}

// ---------------- launcher ----------------
extern "C" void kernel_launch(void* const* d_in, const int* in_sizes, int n_in,
                              void* d_out, int out_size) {
    (void)in_sizes; (void)n_in; (void)out_size;
    const float* x     = (const float*)d_in[0];
    const float* att   = (const float*)d_in[1];
    const float* fwy   = (const float*)d_in[2];
    const float* fwx   = (const float*)d_in[3];
    const float* w1    = (const float*)d_in[4];
    const float* b1    = (const float*)d_in[5];
    const float* w2    = (const float*)d_in[6];
    const float* b2    = (const float*)d_in[7];
    const float* gamma = (const float*)d_in[8];
    const float* beta  = (const float*)d_in[9];
    float* out = (float*)d_out;

    const int SM_FWDY = 16384*4 + 512*8;            // 69632
    const int SM_FWDX = 16384*4 + 510*8;            // 69616
    const int SM_MIX  = 8192*8 + 256*17*8;          // 100352
    const int SM_INVY = (4096 + 512) * 4;
    const int SM_INVX = (4096 + 1020) * 4;
    const int SM_MLP  = (32768 + 256 + 64*3) * 4;

    cudaFuncSetAttribute(k_fwdY, cudaFuncAttributeMaxDynamicSharedMemorySize, SM_FWDY);
    cudaFuncSetAttribute(k_fwdX, cudaFuncAttributeMaxDynamicSharedMemorySize, SM_FWDX);
    cudaFuncSetAttribute(k_mix,  cudaFuncAttributeMaxDynamicSharedMemorySize, SM_MIX);
    cudaFuncSetAttribute(k_mlp,  cudaFuncAttributeMaxDynamicSharedMemorySize, SM_MLP);

    k_weights<<<(BATCH*MODES*CI*CO)/256, 256>>>(att, fwy, fwx);
    k_fwdY<<<BATCH*MM, 256, SM_FWDY>>>(x);
    k_fwdX<<<BATCH*NN, 256, SM_FWDX>>>(x);
    k_mix <<<2*BATCH*MODES, 256, SM_MIX>>>();
    k_invY<<<BATCH*MM, 256, SM_INVY>>>();
    k_invX<<<BATCH*NN, 256, SM_INVX>>>();
    k_mlp <<<(BATCH*MM*NN)/256, 256, SM_MLP>>>(w1, b1, w2, b2, gamma, beta, out);
}

// round 4
// speedup vs baseline: 1.6511x; 1.6045x over previous
#include <cuda_runtime.h>
#include <cuda_bf16.h>
#include <cstdint>

#define BATCH 8
#define MM 256
#define NN 256
#define CI 64
#define CO 64
#define KK 4
#define MODES 32

typedef unsigned long long u64;

__device__ __forceinline__ u64 pk2(float lo, float hi) {
    u64 r; asm("mov.b64 %0,{%1,%2};" : "=l"(r) : "f"(lo), "f"(hi)); return r;
}
__device__ __forceinline__ void upk2(u64 v, float& a, float& b) {
    asm("mov.b64 {%0,%1},%2;" : "=f"(a), "=f"(b) : "l"(v));
}
__device__ __forceinline__ u64 ffma2(u64 a, u64 b, u64 c) {
    u64 d; asm("fma.rn.f32x2 %0,%1,%2,%3;" : "=l"(d) : "l"(a), "l"(b), "l"(c)); return d;
}
__device__ __forceinline__ u64 fmul2(u64 a, u64 b) {
    u64 d; asm("mul.rn.f32x2 %0,%1,%2;" : "=l"(d) : "l"(a), "l"(b)); return d;
}
__device__ __forceinline__ u64 fadd2(u64 a, u64 b) {
    u64 d; asm("add.rn.f32x2 %0,%1,%2;" : "=l"(d) : "l"(a), "l"(b)); return d;
}

// ---------------- scratch ----------------
__device__ float2 g_wy [BATCH*MODES*CI*CO];
__device__ float2 g_wx [BATCH*MODES*CI*CO];
__device__ float2 g_XfY[BATCH*MODES*MM*CI];
__device__ float2 g_XfX[BATCH*MODES*NN*CI];
__device__ float2 g_YfY[BATCH*MODES*MM*CO];
__device__ float2 g_YfX[BATCH*MODES*NN*CO];
__device__ float  g_xsum[(size_t)BATCH*MM*NN*CO];

// pre-split bf16 weight image, laid out exactly like the k_mlp smem block:
// W1hi [n=256][k=64] stride 144B @0 (36864), W1lo @36864,
// W2hi [n=64][k=256] stride 528B @73728 (33792), W2lo @107520. total 141312.
#define W_W1HI 0
#define W_W1LO 36864
#define W_W2HI 73728
#define W_W2LO 107520
#define W_TOT  141312
__device__ __align__(16) unsigned char g_Wimg[W_TOT];

// ---------------- bf16 helpers ----------------
__device__ __forceinline__ void cvt_pair(float v0, float v1, uint32_t& hi, uint32_t& lo) {
    __nv_bfloat16 h0 = __float2bfloat16(v0), h1 = __float2bfloat16(v1);
    float r0 = v0 - __bfloat162float(h0);
    float r1 = v1 - __bfloat162float(h1);
    hi = (uint32_t)__bfloat16_as_ushort(h0) | ((uint32_t)__bfloat16_as_ushort(h1) << 16);
    lo = (uint32_t)__bfloat16_as_ushort(__float2bfloat16(r0))
       | ((uint32_t)__bfloat16_as_ushort(__float2bfloat16(r1)) << 16);
}
__device__ __forceinline__ void mma_bf16(float* d, const uint32_t* a, uint32_t b0, uint32_t b1) {
    asm volatile(
        "mma.sync.aligned.m16n8k16.row.col.f32.bf16.bf16.f32 "
        "{%0,%1,%2,%3},{%4,%5,%6,%7},{%8,%9},{%0,%1,%2,%3};"
        : "+f"(d[0]), "+f"(d[1]), "+f"(d[2]), "+f"(d[3])
        : "r"(a[0]), "r"(a[1]), "r"(a[2]), "r"(a[3]), "r"(b0), "r"(b1));
}

// ---------------- K0: spectral weights ----------------
__global__ void k_weights(const float* __restrict__ att,
                          const float* __restrict__ fwy,
                          const float* __restrict__ fwx) {
    int gid = blockIdx.x * 256 + threadIdx.x;
    int o = gid & 63, i = (gid >> 6) & 63, f = (gid >> 12) & 31, b = gid >> 17;
    float a0 = att[b*KK+0], a1 = att[b*KK+1], a2 = att[b*KK+2], a3 = att[b*KK+3];
    const int ks = CI*CO*MODES*2;
    int base = ((i*CO + o)*MODES + f)*2;
    float yr, yi, xr, xi;
    yr = a0*fwy[base   ] + a1*fwy[base+ks   ] + a2*fwy[base+2*ks  ] + a3*fwy[base+3*ks  ];
    yi = a0*fwy[base+1 ] + a1*fwy[base+ks+1 ] + a2*fwy[base+2*ks+1] + a3*fwy[base+3*ks+1];
    xr = a0*fwx[base   ] + a1*fwx[base+ks   ] + a2*fwx[base+2*ks  ] + a3*fwx[base+3*ks  ];
    xi = a0*fwx[base+1 ] + a1*fwx[base+ks+1 ] + a2*fwx[base+2*ks+1] + a3*fwx[base+3*ks+1];
    g_wy[gid] = make_float2(yr, yi);
    g_wx[gid] = make_float2(xr, xi);
}

// ---------------- K0b: split-bf16 weight image ----------------
__global__ void k_wprep(const float* __restrict__ w1, const float* __restrict__ w2) {
    int gid = blockIdx.x * 256 + threadIdx.x;     // 0..32767
    if (gid < 16384) {
        int i = gid >> 8, j = gid & 255;          // w1[i][j], i=64, j=256
        float v = w1[gid];
        uint32_t hi, lo; { uint32_t h2,l2; cvt_pair(v, 0.f, h2, l2); hi = h2 & 0xFFFF; lo = l2 & 0xFFFF; }
        uint32_t off = (uint32_t)j*144 + (uint32_t)i*2;
        *(unsigned short*)(g_Wimg + W_W1HI + off) = (unsigned short)hi;
        *(unsigned short*)(g_Wimg + W_W1LO + off) = (unsigned short)lo;
    } else {
        int idx = gid - 16384;
        int j = idx >> 6, o = idx & 63;           // w2[j][o], j=256, o=64
        float v = w2[idx];
        uint32_t hi, lo; { uint32_t h2,l2; cvt_pair(v, 0.f, h2, l2); hi = h2 & 0xFFFF; lo = l2 & 0xFFFF; }
        uint32_t off = (uint32_t)o*528 + (uint32_t)j*2;
        *(unsigned short*)(g_Wimg + W_W2HI + off) = (unsigned short)hi;
        *(unsigned short*)(g_Wimg + W_W2LO + off) = (unsigned short)lo;
    }
}

// ---------------- K1Y: forward 32-mode DFT along N (packed f32x2) ----------------
__global__ void __launch_bounds__(256) k_fwdY(const float* __restrict__ x) {
    extern __shared__ float smf[];
    float* sx = smf;
    u64* ct2 = (u64*)(smf + 16384);
    u64* st2 = ct2 + 256;
    int t = threadIdx.x;
    int b = blockIdx.x >> 8, m = blockIdx.x & 255;
    const float4* xr4 = (const float4*)(x + ((size_t)(b*MM + m))*NN*CI);
    float4* sx4 = (float4*)sx;
    #pragma unroll
    for (int it = 0; it < 16; it++) sx4[it*256 + t] = xr4[it*256 + t];
    {
        float c = cospif(t * (1.0f/128.0f));
        float s = sinpif(t * (1.0f/128.0f));
        ct2[t] = pk2(c, c);
        st2[t] = pk2(-s, -s);
    }
    __syncthreads();

    int f = t >> 3, ib = (t & 7) * 8;
    u64 re2[4] = {0,0,0,0}, im2[4] = {0,0,0,0};
    int idx = 0;
    for (int n = 0; n < NN; n++) {
        u64 cc = ct2[idx], ss = st2[idx];
        idx = (idx + f) & 255;
        const ulonglong2* sv = (const ulonglong2*)(sx + n*CI + ib);
        ulonglong2 p0 = sv[0], p1 = sv[1];
        re2[0] = ffma2(p0.x, cc, re2[0]);  im2[0] = ffma2(p0.x, ss, im2[0]);
        re2[1] = ffma2(p0.y, cc, re2[1]);  im2[1] = ffma2(p0.y, ss, im2[1]);
        re2[2] = ffma2(p1.x, cc, re2[2]);  im2[2] = ffma2(p1.x, ss, im2[2]);
        re2[3] = ffma2(p1.y, cc, re2[3]);  im2[3] = ffma2(p1.y, ss, im2[3]);
    }
    const u64 sc2 = pk2(0.0625f, 0.0625f);
    float4* out4 = (float4*)(g_XfY + ((size_t)(b*MODES + f)*MM + m)*CI + ib);
    #pragma unroll
    for (int q = 0; q < 4; q++) {
        float ra, rb, ia, ib2;
        upk2(fmul2(re2[q], sc2), ra, rb);
        upk2(fmul2(im2[q], sc2), ia, ib2);
        out4[q] = make_float4(ra, ia, rb, ib2);
    }
}

// ---------------- K1X: forward sine transform along M (packed) ----------------
__global__ void __launch_bounds__(256) k_fwdX(const float* __restrict__ x) {
    extern __shared__ float smf[];
    float* sx  = smf;
    u64* st5 = (u64*)(smf + 16384);
    int t = threadIdx.x;
    int b = blockIdx.x >> 8, n = blockIdx.x & 255;
    {
        int i4 = (t & 15) * 4;
        int mb = t >> 4;
        #pragma unroll
        for (int j = 0; j < 16; j++) {
            int m = j*16 + mb;
            *(float4*)(sx + m*CI + i4) =
                *(const float4*)(x + (((size_t)(b*MM + m))*NN + n)*CI + i4);
        }
    }
    {
        float s = sinpif(t * (1.0f/255.0f));
        st5[t] = pk2(-s, -s);
        if (t + 256 < 510) {
            float s2 = sinpif((t+256) * (1.0f/255.0f));
            st5[t+256] = pk2(-s2, -s2);
        }
    }
    __syncthreads();

    int f = t >> 3, ib = (t & 7) * 8;
    u64 im2[4] = {0,0,0,0};
    int idx = f;
    for (int m = 1; m <= 254; m++) {
        u64 ss = st5[idx];
        idx += f; if (idx >= 510) idx -= 510;
        const ulonglong2* sv = (const ulonglong2*)(sx + m*CI + ib);
        ulonglong2 p0 = sv[0], p1 = sv[1];
        im2[0] = ffma2(p0.x, ss, im2[0]);
        im2[1] = ffma2(p0.y, ss, im2[1]);
        im2[2] = ffma2(p1.x, ss, im2[2]);
        im2[3] = ffma2(p1.y, ss, im2[3]);
    }
    const float inv = 0.04428074428f;
    float sgn = (f & 1) ? -1.f : 1.f;
    float4* out4 = (float4*)(g_XfX + ((size_t)(b*MODES + f)*NN + n)*CI + ib);
    #pragma unroll
    for (int q = 0; q < 4; q++) {
        float ia, ib2;
        upk2(im2[q], ia, ib2);
        int r0 = 2*q, r1 = 2*q + 1;
        float reA = (sx[ib + r0] + sgn * sx[255*CI + ib + r0]) * inv;
        float reB = (sx[ib + r1] + sgn * sx[255*CI + ib + r1]) * inv;
        out4[q] = make_float4(reA, 2.f*inv*ia, reB, 2.f*inv*ib2);
    }
}

// ---------------- K2: complex GEMM (scalar, proven fastest) ----------------
__global__ void __launch_bounds__(256) k_mix() {
    extern __shared__ float smf[];
    float2* Ws = (float2*)smf;
    float2* As = Ws + 4096;
    int t = threadIdx.x;
    int z = blockIdx.x;
    int branch = z >> 8;
    int bf = z & 255;
    const float2* A = (branch ? g_XfX : g_XfY) + (size_t)bf*MM*CI;
    const float2* W = (branch ? g_wx  : g_wy ) + (size_t)bf*CI*CO;
    float2*       C = (branch ? g_YfX : g_YfY) + (size_t)bf*MM*CO;

    #pragma unroll
    for (int it = 0; it < 16; it++) Ws[it*256 + t] = W[it*256 + t];

    float2 acc[8][8];
    #pragma unroll
    for (int r = 0; r < 8; r++)
        #pragma unroll
        for (int c = 0; c < 8; c++) acc[r][c] = make_float2(0.f, 0.f);

    int m0 = (t >> 3) * 8, o0 = (t & 7) * 8;
    for (int kc = 0; kc < 4; kc++) {
        __syncthreads();
        #pragma unroll
        for (int it = 0; it < 16; it++) {
            int flat = it*256 + t;
            int row = flat >> 4, col = flat & 15;
            As[row*17 + col] = A[row*64 + kc*16 + col];
        }
        __syncthreads();
        #pragma unroll
        for (int ii = 0; ii < 16; ii++) {
            int i = kc*16 + ii;
            float2 a[8], w[8];
            #pragma unroll
            for (int r = 0; r < 8; r++) a[r] = As[(m0 + r)*17 + ii];
            #pragma unroll
            for (int c = 0; c < 8; c++) w[c] = Ws[i*64 + o0 + c];
            #pragma unroll
            for (int r = 0; r < 8; r++)
                #pragma unroll
                for (int c = 0; c < 8; c++) {
                    acc[r][c].x = fmaf(a[r].x, w[c].x, fmaf(-a[r].y, w[c].y, acc[r][c].x));
                    acc[r][c].y = fmaf(a[r].x, w[c].y, fmaf( a[r].y, w[c].x, acc[r][c].y));
                }
        }
    }
    #pragma unroll
    for (int r = 0; r < 8; r++)
        #pragma unroll
        for (int c = 0; c < 8; c++)
            C[(size_t)(m0 + r)*CO + o0 + c] = acc[r][c];
}

// ---------------- K3Y: inverse synthesis along N (packed) ----------------
__global__ void __launch_bounds__(256) k_invY() {
    extern __shared__ float smf[];
    float* cre = smf;
    float* cim = smf + 2048;
    float* ct  = smf + 4096;
    float* st  = ct + 256;
    int t = threadIdx.x;
    int b = blockIdx.x >> 8, m = blockIdx.x & 255;
    const float2* Y = g_YfY + ((size_t)b*MODES*MM + m)*CO;
    #pragma unroll
    for (int it = 0; it < 8; it++) {
        int flat = it*256 + t;
        int f = flat >> 6;
        float2 v = Y[(size_t)f*MM*CO + (flat & 63)];
        cre[flat] = v.x * ((f == 0) ? 0.0625f : 0.125f);
        cim[flat] = v.y * 0.125f;
    }
    ct[t] = cospif(t * (1.0f/128.0f));
    st[t] = sinpif(t * (1.0f/128.0f));
    __syncthreads();

    int n = t;
    u64 acc[32];
    #pragma unroll
    for (int q = 0; q < 32; q++) acc[q] = 0;
    int idx = 0;
    for (int f = 0; f < MODES; f++) {
        float c = ct[idx], s = st[idx];
        idx = (idx + n) & 255;
        u64 cc = pk2(c, c), ss = pk2(-s, -s);
        const ulonglong2* r2 = (const ulonglong2*)(cre + f*64);
        const ulonglong2* i2 = (const ulonglong2*)(cim + f*64);
        #pragma unroll
        for (int q = 0; q < 16; q++) {
            ulonglong2 rp = r2[q], ip = i2[q];
            acc[2*q  ] = ffma2(rp.x, cc, ffma2(ip.x, ss, acc[2*q  ]));
            acc[2*q+1] = ffma2(rp.y, cc, ffma2(ip.y, ss, acc[2*q+1]));
        }
    }
    ulonglong2* out = (ulonglong2*)(g_xsum + (((size_t)(b*MM + m))*NN + n)*CO);
    #pragma unroll
    for (int q = 0; q < 16; q++) {
        ulonglong2 v; v.x = acc[2*q]; v.y = acc[2*q+1];
        out[q] = v;
    }
}

// ---------------- K3X: inverse synthesis along M, accumulate (packed) ----------------
__global__ void __launch_bounds__(256) k_invX() {
    extern __shared__ float smf[];
    float* cre = smf;
    float* cim = smf + 2048;
    float* ct5 = smf + 4096;
    float* st5 = ct5 + 510;
    int t = threadIdx.x;
    int b = blockIdx.x >> 8, n = blockIdx.x & 255;
    const float inv = 0.04428074428f;
    const float2* Y = g_YfX + ((size_t)b*MODES*NN + n)*CO;
    #pragma unroll
    for (int it = 0; it < 8; it++) {
        int flat = it*256 + t;
        int f = flat >> 6;
        float2 v = Y[(size_t)f*NN*CO + (flat & 63)];
        cre[flat] = v.x * (((f == 0) ? 1.f : 2.f) * inv);
        cim[flat] = v.y * (2.f * inv);
    }
    ct5[t] = cospif(t * (1.0f/255.0f));
    st5[t] = sinpif(t * (1.0f/255.0f));
    if (t + 256 < 510) {
        ct5[t+256] = cospif((t+256) * (1.0f/255.0f));
        st5[t+256] = sinpif((t+256) * (1.0f/255.0f));
    }
    __syncthreads();

    int m = t;
    u64 acc[32];
    #pragma unroll
    for (int q = 0; q < 32; q++) acc[q] = 0;
    int idx = 0;
    for (int f = 0; f < MODES; f++) {
        float c = ct5[idx], s = st5[idx];
        idx += m; if (idx >= 510) idx -= 510;
        u64 cc = pk2(c, c), ss = pk2(-s, -s);
        const ulonglong2* r2 = (const ulonglong2*)(cre + f*64);
        const ulonglong2* i2 = (const ulonglong2*)(cim + f*64);
        #pragma unroll
        for (int q = 0; q < 16; q++) {
            ulonglong2 rp = r2[q], ip = i2[q];
            acc[2*q  ] = ffma2(rp.x, cc, ffma2(ip.x, ss, acc[2*q  ]));
            acc[2*q+1] = ffma2(rp.y, cc, ffma2(ip.y, ss, acc[2*q+1]));
        }
    }
    ulonglong2* out = (ulonglong2*)(g_xsum + (((size_t)(b*MM + m))*NN + n)*CO);
    #pragma unroll
    for (int q = 0; q < 16; q++) {
        ulonglong2 v = out[q];
        v.x = fadd2(v.x, acc[2*q]);
        v.y = fadd2(v.y, acc[2*q+1]);
        out[q] = v;
    }
}

// ---------------- K4: MLP via mma.sync bf16 split + LayerNorm ----------------
// smem byte map:
#define SA_HI   0            // A hi  [256 rows][stride 144]
#define SA_LO   36864        // A lo
#define SW_BASE 73728        // weight image copied verbatim (141312 B)
#define S_B1    215040       // 256 floats
#define S_B2    216064       // 64
#define S_GAM   216320
#define S_BET   216576
#define SM_MLP  216832

__global__ void __launch_bounds__(256) k_mlp_mma(const float* __restrict__ b1,
                                                 const float* __restrict__ b2,
                                                 const float* __restrict__ gamma,
                                                 const float* __restrict__ beta,
                                                 float* __restrict__ out) {
    extern __shared__ __align__(16) unsigned char sm[];
    int t = threadIdx.x;
    int w = t >> 5, l = t & 31;
    int l4 = l >> 2, lq = l & 3;

    // bulk copy weight image
    {
        const float4* src = (const float4*)g_Wimg;
        float4* dst = (float4*)(sm + SW_BASE);
        for (int i = t; i < W_TOT/16; i += 256) dst[i] = src[i];
    }
    float* b1s = (float*)(sm + S_B1);
    float* b2s = (float*)(sm + S_B2);
    float* gs  = (float*)(sm + S_GAM);
    float* bs  = (float*)(sm + S_BET);
    b1s[t] = b1[t];
    if (t < 64) { b2s[t] = b2[t]; gs[t] = gamma[t]; bs[t] = beta[t]; }

    // stage A tile: thread t = row t
    {
        const float4* xs = (const float4*)(g_xsum + ((size_t)blockIdx.x*256 + t)*64);
        unsigned char* rh = sm + SA_HI + t*144;
        unsigned char* rl = sm + SA_LO + t*144;
        #pragma unroll
        for (int q = 0; q < 16; q++) {
            float4 v = xs[q];
            uint32_t h0, l0, h1, l1;
            cvt_pair(v.x, v.y, h0, l0);
            cvt_pair(v.z, v.w, h1, l1);
            *(uint32_t*)(rh + q*8    ) = h0;
            *(uint32_t*)(rh + q*8 + 4) = h1;
            *(uint32_t*)(rl + q*8    ) = l0;
            *(uint32_t*)(rl + q*8 + 4) = l1;
        }
    }
    __syncthreads();

    float d2[2][8][4];
    #pragma unroll
    for (int mt = 0; mt < 2; mt++)
        #pragma unroll
        for (int j = 0; j < 8; j++)
            #pragma unroll
            for (int q = 0; q < 4; q++) d2[mt][j][q] = 0.f;

    const unsigned char* W1h = sm + SW_BASE + W_W1HI;
    const unsigned char* W1l = sm + SW_BASE + W_W1LO;
    const unsigned char* W2h = sm + SW_BASE + W_W2HI;
    const unsigned char* W2l = sm + SW_BASE + W_W2LO;

    for (int c = 0; c < 4; c++) {
        // ---- layer 1: H chunk [256 x 64] ----
        float h[2][8][4];
        #pragma unroll
        for (int mt = 0; mt < 2; mt++)
            #pragma unroll
            for (int j = 0; j < 8; j++)
                #pragma unroll
                for (int q = 0; q < 4; q++) h[mt][j][q] = 0.f;

        #pragma unroll
        for (int kt = 0; kt < 4; kt++) {
            uint32_t ah[2][4], al[2][4];
            #pragma unroll
            for (int mt = 0; mt < 2; mt++) {
                int row = w*32 + mt*16 + l4;
                int kof = (kt*16 + 2*lq)*2;
                ah[mt][0] = *(const uint32_t*)(sm + SA_HI + row*144 + kof);
                ah[mt][1] = *(const uint32_t*)(sm + SA_HI + (row+8)*144 + kof);
                ah[mt][2] = *(const uint32_t*)(sm + SA_HI + row*144 + kof + 16);
                ah[mt][3] = *(const uint32_t*)(sm + SA_HI + (row+8)*144 + kof + 16);
                al[mt][0] = *(const uint32_t*)(sm + SA_LO + row*144 + kof);
                al[mt][1] = *(const uint32_t*)(sm + SA_LO + (row+8)*144 + kof);
                al[mt][2] = *(const uint32_t*)(sm + SA_LO + row*144 + kof + 16);
                al[mt][3] = *(const uint32_t*)(sm + SA_LO + (row+8)*144 + kof + 16);
            }
            #pragma unroll
            for (int j = 0; j < 8; j++) {
                int n = c*64 + j*8 + l4;
                int kof = (kt*16 + 2*lq)*2;
                uint32_t bh0 = *(const uint32_t*)(W1h + n*144 + kof);
                uint32_t bh1 = *(const uint32_t*)(W1h + n*144 + kof + 16);
                uint32_t bl0 = *(const uint32_t*)(W1l + n*144 + kof);
                uint32_t bl1 = *(const uint32_t*)(W1l + n*144 + kof + 16);
                #pragma unroll
                for (int mt = 0; mt < 2; mt++) {
                    mma_bf16(h[mt][j], ah[mt], bh0, bh1);
                    mma_bf16(h[mt][j], ah[mt], bl0, bl1);
                    mma_bf16(h[mt][j], al[mt], bh0, bh1);
                }
            }
        }

        // ---- bias + relu + split → layer2 A-fragments, then layer2 MMA ----
        #pragma unroll
        for (int kt2 = 0; kt2 < 4; kt2++) {
            int j = 2*kt2;
            uint32_t ah2[2][4], al2[2][4];
            #pragma unroll
            for (int mt = 0; mt < 2; mt++) {
                int g0 = c*64 + j*8 + 2*lq;
                float bA = b1s[g0],   bB = b1s[g0+1];
                float bC = b1s[g0+8], bD = b1s[g0+9];
                float v0 = fmaxf(h[mt][j][0] + bA, 0.f);
                float v1 = fmaxf(h[mt][j][1] + bB, 0.f);
                cvt_pair(v0, v1, ah2[mt][0], al2[mt][0]);
                v0 = fmaxf(h[mt][j][2] + bA, 0.f);
                v1 = fmaxf(h[mt][j][3] + bB, 0.f);
                cvt_pair(v0, v1, ah2[mt][1], al2[mt][1]);
                v0 = fmaxf(h[mt][j+1][0] + bC, 0.f);
                v1 = fmaxf(h[mt][j+1][1] + bD, 0.f);
                cvt_pair(v0, v1, ah2[mt][2], al2[mt][2]);
                v0 = fmaxf(h[mt][j+1][2] + bC, 0.f);
                v1 = fmaxf(h[mt][j+1][3] + bD, 0.f);
                cvt_pair(v0, v1, ah2[mt][3], al2[mt][3]);
            }
            int k0 = c*64 + kt2*16;
            #pragma unroll
            for (int j2 = 0; j2 < 8; j2++) {
                int n = j2*8 + l4;
                int kof = (k0 + 2*lq)*2;
                uint32_t bh0 = *(const uint32_t*)(W2h + n*528 + kof);
                uint32_t bh1 = *(const uint32_t*)(W2h + n*528 + kof + 16);
                uint32_t bl0 = *(const uint32_t*)(W2l + n*528 + kof);
                uint32_t bl1 = *(const uint32_t*)(W2l + n*528 + kof + 16);
                #pragma unroll
                for (int mt = 0; mt < 2; mt++) {
                    mma_bf16(d2[mt][j2], ah2[mt], bh0, bh1);
                    mma_bf16(d2[mt][j2], ah2[mt], bl0, bl1);
                    mma_bf16(d2[mt][j2], al2[mt], bh0, bh1);
                }
            }
        }
    }

    // ---- +b2, LayerNorm over 64, write out ----
    #pragma unroll
    for (int mt = 0; mt < 2; mt++) {
        #pragma unroll
        for (int rh = 0; rh < 2; rh++) {
            float vals[16];
            #pragma unroll
            for (int j2 = 0; j2 < 8; j2++) {
                int col = j2*8 + 2*lq;
                vals[2*j2  ] = d2[mt][j2][2*rh  ] + b2s[col];
                vals[2*j2+1] = d2[mt][j2][2*rh+1] + b2s[col+1];
            }
            float s = 0.f;
            #pragma unroll
            for (int q = 0; q < 16; q++) s += vals[q];
            s += __shfl_xor_sync(0xffffffffu, s, 1);
            s += __shfl_xor_sync(0xffffffffu, s, 2);
            float mu = s * (1.f/64.f);
            float v = 0.f;
            #pragma unroll
            for (int q = 0; q < 16; q++) { float d = vals[q] - mu; v = fmaf(d, d, v); }
            v += __shfl_xor_sync(0xffffffffu, v, 1);
            v += __shfl_xor_sync(0xffffffffu, v, 2);
            float rinv = rsqrtf(v * (1.f/64.f) + 1e-5f);
            size_t row = (size_t)blockIdx.x*256 + w*32 + mt*16 + rh*8 + l4;
            #pragma unroll
            for (int j2 = 0; j2 < 8; j2++) {
                int col = j2*8 + 2*lq;
                float2 r;
                r.x = (vals[2*j2  ] - mu) * rinv * gs[col  ] + bs[col  ];
                r.y = (vals[2*j2+1] - mu) * rinv * gs[col+1] + bs[col+1];
                *(float2*)(out + row*64 + col) = r;
            }
        }
    }
}

// ---------------- launcher ----------------
extern "C" void kernel_launch(void* const* d_in, const int* in_sizes, int n_in,
                              void* d_out, int out_size) {
    (void)in_sizes; (void)n_in; (void)out_size;
    const float* x     = (const float*)d_in[0];
    const float* att   = (const float*)d_in[1];
    const float* fwy   = (const float*)d_in[2];
    const float* fwx   = (const float*)d_in[3];
    const float* w1    = (const float*)d_in[4];
    const float* b1    = (const float*)d_in[5];
    const float* w2    = (const float*)d_in[6];
    const float* b2    = (const float*)d_in[7];
    const float* gamma = (const float*)d_in[8];
    const float* beta  = (const float*)d_in[9];
    float* out = (float*)d_out;

    const int SM_FWDY = 16384*4 + 512*8;
    const int SM_FWDX = 16384*4 + 510*8;
    const int SM_MIX  = (4096 + 256*17) * 8;
    const int SM_INVY = (4096 + 512) * 4;
    const int SM_INVX = (4096 + 1020) * 4;

    cudaFuncSetAttribute(k_fwdY,    cudaFuncAttributeMaxDynamicSharedMemorySize, SM_FWDY);
    cudaFuncSetAttribute(k_fwdX,    cudaFuncAttributeMaxDynamicSharedMemorySize, SM_FWDX);
    cudaFuncSetAttribute(k_mix,     cudaFuncAttributeMaxDynamicSharedMemorySize, SM_MIX);
    cudaFuncSetAttribute(k_mlp_mma, cudaFuncAttributeMaxDynamicSharedMemorySize, SM_MLP);

    k_weights<<<(BATCH*MODES*CI*CO)/256, 256>>>(att, fwy, fwx);
    k_wprep<<<128, 256>>>(w1, w2);
    k_fwdY<<<BATCH*MM, 256, SM_FWDY>>>(x);
    k_fwdX<<<BATCH*NN, 256, SM_FWDX>>>(x);
    k_mix <<<2*BATCH*MODES, 256, SM_MIX>>>();
    k_invY<<<BATCH*MM, 256, SM_INVY>>>();
    k_invX<<<BATCH*NN, 256, SM_INVX>>>();
    k_mlp_mma<<<(BATCH*MM*NN)/256, 256, SM_MLP>>>(b1, b2, gamma, beta, out);
}

// round 5
// speedup vs baseline: 2.3523x; 1.4247x over previous
#include <cuda_runtime.h>
#include <cuda_bf16.h>
#include <cstdint>

#define BATCH 8
#define MM 256
#define NN 256
#define CI 64
#define CO 64
#define KK 4
#define MODES 32

typedef unsigned long long u64;

// ---------------- scratch ----------------
__device__ float2 g_wy [BATCH*MODES*CI*CO];
__device__ float2 g_wx [BATCH*MODES*CI*CO];
__device__ float2 g_XfY[BATCH*MODES*MM*CI];
__device__ float2 g_XfX[BATCH*MODES*NN*CI];
__device__ float2 g_YfY[BATCH*MODES*MM*CO];
__device__ float2 g_YfX[BATCH*MODES*NN*CO];
__device__ float  g_xsum[(size_t)BATCH*MM*NN*CO];

// pre-split bf16 weight image for the MLP (layout == k_mlp smem block)
#define W_W1HI 0
#define W_W1LO 36864
#define W_W2HI 73728
#define W_W2LO 107520
#define W_TOT  141312
__device__ __align__(16) unsigned char g_Wimg[W_TOT];

// ---------------- bf16 helpers ----------------
__device__ __forceinline__ void cvt_pair(float v0, float v1, uint32_t& hi, uint32_t& lo) {
    __nv_bfloat16 h0 = __float2bfloat16(v0), h1 = __float2bfloat16(v1);
    float r0 = v0 - __bfloat162float(h0);
    float r1 = v1 - __bfloat162float(h1);
    hi = (uint32_t)__bfloat16_as_ushort(h0) | ((uint32_t)__bfloat16_as_ushort(h1) << 16);
    lo = (uint32_t)__bfloat16_as_ushort(__float2bfloat16(r0))
       | ((uint32_t)__bfloat16_as_ushort(__float2bfloat16(r1)) << 16);
}
__device__ __forceinline__ void mma_bf16(float* d, const uint32_t* a, uint32_t b0, uint32_t b1) {
    asm volatile(
        "mma.sync.aligned.m16n8k16.row.col.f32.bf16.bf16.f32 "
        "{%0,%1,%2,%3},{%4,%5,%6,%7},{%8,%9},{%0,%1,%2,%3};"
        : "+f"(d[0]), "+f"(d[1]), "+f"(d[2]), "+f"(d[3])
        : "r"(a[0]), "r"(a[1]), "r"(a[2]), "r"(a[3]), "r"(b0), "r"(b1));
}

// ---------------- K0: spectral weights ----------------
__global__ void k_weights(const float* __restrict__ att,
                          const float* __restrict__ fwy,
                          const float* __restrict__ fwx) {
    int gid = blockIdx.x * 256 + threadIdx.x;
    int o = gid & 63, i = (gid >> 6) & 63, f = (gid >> 12) & 31, b = gid >> 17;
    float a0 = att[b*KK+0], a1 = att[b*KK+1], a2 = att[b*KK+2], a3 = att[b*KK+3];
    const int ks = CI*CO*MODES*2;
    int base = ((i*CO + o)*MODES + f)*2;
    float yr, yi, xr, xi;
    yr = a0*fwy[base   ] + a1*fwy[base+ks   ] + a2*fwy[base+2*ks  ] + a3*fwy[base+3*ks  ];
    yi = a0*fwy[base+1 ] + a1*fwy[base+ks+1 ] + a2*fwy[base+2*ks+1] + a3*fwy[base+3*ks+1];
    xr = a0*fwx[base   ] + a1*fwx[base+ks   ] + a2*fwx[base+2*ks  ] + a3*fwx[base+3*ks  ];
    xi = a0*fwx[base+1 ] + a1*fwx[base+ks+1 ] + a2*fwx[base+2*ks+1] + a3*fwx[base+3*ks+1];
    g_wy[gid] = make_float2(yr, yi);
    g_wx[gid] = make_float2(xr, xi);
}

// ---------------- K0b: split-bf16 weight image for MLP ----------------
__global__ void k_wprep(const float* __restrict__ w1, const float* __restrict__ w2) {
    int gid = blockIdx.x * 256 + threadIdx.x;     // 0..32767
    if (gid < 16384) {
        int i = gid >> 8, j = gid & 255;
        float v = w1[gid];
        uint32_t hi, lo; { uint32_t h2,l2; cvt_pair(v, 0.f, h2, l2); hi = h2 & 0xFFFF; lo = l2 & 0xFFFF; }
        uint32_t off = (uint32_t)j*144 + (uint32_t)i*2;
        *(unsigned short*)(g_Wimg + W_W1HI + off) = (unsigned short)hi;
        *(unsigned short*)(g_Wimg + W_W1LO + off) = (unsigned short)lo;
    } else {
        int idx = gid - 16384;
        int j = idx >> 6, o = idx & 63;
        float v = w2[idx];
        uint32_t hi, lo; { uint32_t h2,l2; cvt_pair(v, 0.f, h2, l2); hi = h2 & 0xFFFF; lo = l2 & 0xFFFF; }
        uint32_t off = (uint32_t)o*528 + (uint32_t)j*2;
        *(unsigned short*)(g_Wimg + W_W2HI + off) = (unsigned short)hi;
        *(unsigned short*)(g_Wimg + W_W2LO + off) = (unsigned short)lo;
    }
}

// ---------------- K1Y: forward 32-mode DFT along N (register-blocked) ----------------
// block = (b,m). 256 threads: ns(4 n-quarters) x fq(8, 4 freqs each) x cg(8, 8 chans each)
__global__ void __launch_bounds__(256) k_fwdY(const float* __restrict__ x) {
    extern __shared__ float smf[];
    float* sx = smf;               // [n=256][64] = 16384 floats (also reused for partials: 64*260)
    float* ct = smf + 16640;       // 256
    float* st = smf + 16896;       // 256
    int t = threadIdx.x;
    int b = blockIdx.x >> 8, m = blockIdx.x & 255;
    const float4* xr4 = (const float4*)(x + ((size_t)(b*MM + m))*NN*CI);
    float4* sx4 = (float4*)sx;
    #pragma unroll
    for (int it = 0; it < 16; it++) sx4[it*256 + t] = xr4[it*256 + t];
    ct[t] = cospif(t * (1.0f/128.0f));
    st[t] = sinpif(t * (1.0f/128.0f));
    __syncthreads();

    int ns = t >> 6, fq = (t >> 3) & 7, cg = t & 7;
    int f0 = fq*4, ib = cg*8;
    int n0 = ns*64;
    int idxs[4];
    #pragma unroll
    for (int ff = 0; ff < 4; ff++) idxs[ff] = ((f0 + ff) * n0) & 255;

    float are[4][8], aim[4][8];
    #pragma unroll
    for (int ff = 0; ff < 4; ff++)
        #pragma unroll
        for (int ch = 0; ch < 8; ch++) { are[ff][ch] = 0.f; aim[ff][ch] = 0.f; }

    for (int j = 0; j < 64; j++) {
        int n = n0 + j;
        const float4* xv = (const float4*)(sx + n*64 + ib);
        float4 v0 = xv[0], v1 = xv[1];
        float xv8[8] = {v0.x, v0.y, v0.z, v0.w, v1.x, v1.y, v1.z, v1.w};
        #pragma unroll
        for (int ff = 0; ff < 4; ff++) {
            float c = ct[idxs[ff]], s = st[idxs[ff]];
            idxs[ff] = (idxs[ff] + f0 + ff) & 255;
            #pragma unroll
            for (int ch = 0; ch < 8; ch++) {
                are[ff][ch] = fmaf(xv8[ch], c, are[ff][ch]);
                aim[ff][ch] = fmaf(xv8[ch], s, aim[ff][ch]);
            }
        }
    }

    __syncthreads();                    // all sx reads done
    // partials: part[g=fq*8+cg][ns][ff*16 + reim*8 + ch], stride 260
    {
        float* pdst = sx + (fq*8 + cg)*260 + ns*64;
        #pragma unroll
        for (int ff = 0; ff < 4; ff++)
            #pragma unroll
            for (int ch = 0; ch < 8; ch++) {
                pdst[ff*16 + ch]     = are[ff][ch];
                pdst[ff*16 + 8 + ch] = aim[ff][ch];
            }
    }
    __syncthreads();

    // reduce + store: thread owns g2 = t>>2, ff2 = t&3 -> 8 channels
    int g2 = t >> 2, ff2 = t & 3;
    int fq2 = g2 >> 3, cg2 = g2 & 7;
    int f = fq2*4 + ff2;
    float re8[8], im8[8];
    #pragma unroll
    for (int ch = 0; ch < 8; ch++) { re8[ch] = 0.f; im8[ch] = 0.f; }
    #pragma unroll
    for (int q = 0; q < 4; q++) {
        const float* ps = sx + g2*260 + q*64 + ff2*16;
        #pragma unroll
        for (int ch = 0; ch < 8; ch++) { re8[ch] += ps[ch]; im8[ch] += ps[8 + ch]; }
    }
    const float sc = 0.0625f;          // 1/sqrt(256)
    float4* dst = (float4*)(g_XfY + ((size_t)(b*MODES + f)*MM + m)*CI + cg2*8);
    #pragma unroll
    for (int u = 0; u < 4; u++)
        dst[u] = make_float4(re8[2*u]*sc, -im8[2*u]*sc, re8[2*u+1]*sc, -im8[2*u+1]*sc);
}

// ---------------- K1X: forward sine transform along M (register-blocked) ----------------
__global__ void __launch_bounds__(256) k_fwdX(const float* __restrict__ x) {
    extern __shared__ float smf[];
    float* sx   = smf;              // [m=256][64]; reused for partials 64*132
    float* st5  = smf + 16384;      // 510
    float* ebuf = smf + 16896;      // 128 (x[0][ch], x[255][ch])
    int t = threadIdx.x;
    int b = blockIdx.x >> 8, n = blockIdx.x & 255;
    {
        int i4 = (t & 15) * 4;
        int mb = t >> 4;
        #pragma unroll
        for (int j = 0; j < 16; j++) {
            int m = j*16 + mb;
            *(float4*)(sx + m*CI + i4) =
                *(const float4*)(x + (((size_t)(b*MM + m))*NN + n)*CI + i4);
        }
    }
    st5[t] = sinpif(t * (1.0f/255.0f));
    if (t + 256 < 510) st5[t+256] = sinpif((t+256) * (1.0f/255.0f));
    __syncthreads();

    int ns = t >> 6, fq = (t >> 3) & 7, cg = t & 7;
    int f0 = fq*4, ib = cg*8;
    int mstart = (ns == 0) ? 1 : ns*64;
    int mend   = (ns == 3) ? 255 : ns*64 + 64;   // exclusive
    int idxs[4];
    #pragma unroll
    for (int ff = 0; ff < 4; ff++) idxs[ff] = ((f0 + ff) * mstart) % 510;

    float aim[4][8];
    #pragma unroll
    for (int ff = 0; ff < 4; ff++)
        #pragma unroll
        for (int ch = 0; ch < 8; ch++) aim[ff][ch] = 0.f;

    for (int mi = mstart; mi < mend; mi++) {
        const float4* xv = (const float4*)(sx + mi*64 + ib);
        float4 v0 = xv[0], v1 = xv[1];
        float xv8[8] = {v0.x, v0.y, v0.z, v0.w, v1.x, v1.y, v1.z, v1.w};
        #pragma unroll
        for (int ff = 0; ff < 4; ff++) {
            float s = st5[idxs[ff]];
            idxs[ff] += f0 + ff; if (idxs[ff] >= 510) idxs[ff] -= 510;
            #pragma unroll
            for (int ch = 0; ch < 8; ch++)
                aim[ff][ch] = fmaf(xv8[ch], s, aim[ff][ch]);
        }
    }

    // save endpoints (rows 0,255 not written by anyone yet)
    if (t < 64)       ebuf[t]      = sx[t];
    else if (t < 128) ebuf[t]      = sx[255*64 + (t - 64)];
    __syncthreads();                 // sx reads done + ebuf visible
    {
        float* pdst = sx + (fq*8 + cg)*132 + ns*32;
        #pragma unroll
        for (int ff = 0; ff < 4; ff++)
            #pragma unroll
            for (int ch = 0; ch < 8; ch++) pdst[ff*8 + ch] = aim[ff][ch];
    }
    __syncthreads();

    int g2 = t >> 2, ff2 = t & 3;
    int fq2 = g2 >> 3, cg2 = g2 & 7;
    int f = fq2*4 + ff2;
    float im8[8];
    #pragma unroll
    for (int ch = 0; ch < 8; ch++) im8[ch] = 0.f;
    #pragma unroll
    for (int q = 0; q < 4; q++) {
        const float* ps = sx + g2*132 + q*32 + ff2*8;
        #pragma unroll
        for (int ch = 0; ch < 8; ch++) im8[ch] += ps[ch];
    }
    const float inv = 0.04428074428f;    // 1/sqrt(510)
    float sgn = (f & 1) ? -1.f : 1.f;
    float4* dst = (float4*)(g_XfX + ((size_t)(b*MODES + f)*NN + n)*CI + cg2*8);
    #pragma unroll
    for (int u = 0; u < 4; u++) {
        int c0 = cg2*8 + 2*u, c1 = c0 + 1;
        float reA = (ebuf[c0] + sgn * ebuf[64 + c0]) * inv;
        float reB = (ebuf[c1] + sgn * ebuf[64 + c1]) * inv;
        dst[u] = make_float4(reA, -2.f*inv*im8[2*u], reB, -2.f*inv*im8[2*u+1]);
    }
}

// ---------------- K2: complex GEMM via mma.sync (real-ified, split bf16) ----------------
#define MX_AHI 0
#define MX_ALO 69632
#define MX_WHI 139264
#define MX_WLO 174080
#define MX_TOT 208896

__global__ void __launch_bounds__(256) k_mix_mma() {
    extern __shared__ __align__(16) unsigned char sm[];
    int t = threadIdx.x, w = t >> 5, l = t & 31, l4 = l >> 2, lq = l & 3;
    int z = blockIdx.x, branch = z >> 8, bf = z & 255;
    const float2* A = (branch ? g_XfX : g_XfY) + (size_t)bf*MM*CI;
    const float2* W = (branch ? g_wx  : g_wy ) + (size_t)bf*CI*CO;
    float2*       C = (branch ? g_YfX : g_YfY) + (size_t)bf*MM*CO;

    // stage A [256 m][128 k] fp32 -> split bf16, stride 272B, SW-free (4*l4+lq banking)
    {
        const float4* Af = (const float4*)A;
        #pragma unroll
        for (int it = 0; it < 32; it++) {
            int ft = it*256 + t;
            int row = ft >> 5, c4 = ft & 31;
            float4 v = Af[ft];
            uint32_t h01, l01, h23, l23;
            cvt_pair(v.x, v.y, h01, l01);
            cvt_pair(v.z, v.w, h23, l23);
            *(uint2*)(sm + MX_AHI + row*272 + c4*8) = make_uint2(h01, h23);
            *(uint2*)(sm + MX_ALO + row*272 + c4*8) = make_uint2(l01, l23);
        }
    }
    // stage W'' transposed: Wt[c=2o+rc][k=2i+rk], stride 272B
    {
        #pragma unroll
        for (int it = 0; it < 16; it++) {
            int flat = it*256 + t;          // 4096 = 64i * 64o
            int i = flat >> 6, o = flat & 63;
            float2 wv = W[flat];
            uint32_t ha, la, hb, lb;
            cvt_pair(wv.x, -wv.y, ha, la);  // row 2o:   (wre, -wim)
            cvt_pair(wv.y,  wv.x, hb, lb);  // row 2o+1: (wim,  wre)
            *(uint32_t*)(sm + MX_WHI + (2*o  )*272 + i*4) = ha;
            *(uint32_t*)(sm + MX_WHI + (2*o+1)*272 + i*4) = hb;
            *(uint32_t*)(sm + MX_WLO + (2*o  )*272 + i*4) = la;
            *(uint32_t*)(sm + MX_WLO + (2*o+1)*272 + i*4) = lb;
        }
    }
    __syncthreads();

    float acc[2][16][4];
    #pragma unroll
    for (int mt = 0; mt < 2; mt++)
        #pragma unroll
        for (int j2 = 0; j2 < 16; j2++)
            #pragma unroll
            for (int q = 0; q < 4; q++) acc[mt][j2][q] = 0.f;

    int m0 = w*32;
    #pragma unroll
    for (int kt = 0; kt < 8; kt++) {
        int kof = kt*32 + lq*4;
        uint32_t ah[2][4], al[2][4];
        #pragma unroll
        for (int mt = 0; mt < 2; mt++) {
            int row = m0 + mt*16 + l4;
            ah[mt][0] = *(const uint32_t*)(sm + MX_AHI + row*272 + kof);
            ah[mt][1] = *(const uint32_t*)(sm + MX_AHI + (row+8)*272 + kof);
            ah[mt][2] = *(const uint32_t*)(sm + MX_AHI + row*272 + kof + 16);
            ah[mt][3] = *(const uint32_t*)(sm + MX_AHI + (row+8)*272 + kof + 16);
            al[mt][0] = *(const uint32_t*)(sm + MX_ALO + row*272 + kof);
            al[mt][1] = *(const uint32_t*)(sm + MX_ALO + (row+8)*272 + kof);
            al[mt][2] = *(const uint32_t*)(sm + MX_ALO + row*272 + kof + 16);
            al[mt][3] = *(const uint32_t*)(sm + MX_ALO + (row+8)*272 + kof + 16);
        }
        #pragma unroll
        for (int j2 = 0; j2 < 16; j2++) {
            int nrow = j2*8 + l4;
            uint32_t bh0 = *(const uint32_t*)(sm + MX_WHI + nrow*272 + kof);
            uint32_t bh1 = *(const uint32_t*)(sm + MX_WHI + nrow*272 + kof + 16);
            uint32_t bl0 = *(const uint32_t*)(sm + MX_WLO + nrow*272 + kof);
            uint32_t bl1 = *(const uint32_t*)(sm + MX_WLO + nrow*272 + kof + 16);
            #pragma unroll
            for (int mt = 0; mt < 2; mt++) {
                mma_bf16(acc[mt][j2], ah[mt], bh0, bh1);
                mma_bf16(acc[mt][j2], ah[mt], bl0, bl1);
                mma_bf16(acc[mt][j2], al[mt], bh0, bh1);
            }
        }
    }

    // epilogue: C cols are interleaved (2o=re, 2o+1=im) == float2 layout of g_Y*
    float* Cf = (float*)C;
    #pragma unroll
    for (int mt = 0; mt < 2; mt++) {
        #pragma unroll
        for (int j2 = 0; j2 < 16; j2++) {
            int row = m0 + mt*16 + l4;
            int col = j2*8 + 2*lq;
            *(float2*)(Cf + (size_t)row*128 + col)     = make_float2(acc[mt][j2][0], acc[mt][j2][1]);
            *(float2*)(Cf + (size_t)(row+8)*128 + col) = make_float2(acc[mt][j2][2], acc[mt][j2][3]);
        }
    }
}

// ---------------- K3Y: inverse synthesis along N (register-blocked) ----------------
// block (b,m). 256 threads: ng(64, 4 n-points strided 64) x cg(4, 16 chans)
__global__ void __launch_bounds__(256) k_invY() {
    extern __shared__ float smf[];
    float* cre = smf;              // [32][64]
    float* cim = smf + 2048;
    float* ct  = smf + 4096;       // 256
    float* st  = smf + 4352;       // 256
    int t = threadIdx.x;
    int b = blockIdx.x >> 8, m = blockIdx.x & 255;
    const float2* Y = g_YfY + ((size_t)b*MODES*MM + m)*CO;
    #pragma unroll
    for (int it = 0; it < 8; it++) {
        int flat = it*256 + t;
        int f = flat >> 6;
        float2 v = Y[(size_t)f*MM*CO + (flat & 63)];
        cre[flat] = v.x * ((f == 0) ? 0.0625f : 0.125f);
        cim[flat] = v.y * (-0.125f);        // sign baked: result = sum cre*c + cim*s
    }
    ct[t] = cospif(t * (1.0f/128.0f));
    st[t] = sinpif(t * (1.0f/128.0f));
    __syncthreads();

    int ng = t >> 2, cg = t & 3;
    int ch0 = cg * 16;
    int nq[4], idx[4];
    #pragma unroll
    for (int q = 0; q < 4; q++) { nq[q] = ng + 64*q; idx[q] = 0; }

    float acc[4][16];
    #pragma unroll
    for (int q = 0; q < 4; q++)
        #pragma unroll
        for (int ch = 0; ch < 16; ch++) acc[q][ch] = 0.f;

    for (int f = 0; f < MODES; f++) {
        float cq[4], sq[4];
        #pragma unroll
        for (int q = 0; q < 4; q++) {
            cq[q] = ct[idx[q]]; sq[q] = st[idx[q]];
            idx[q] = (idx[q] + nq[q]) & 255;
        }
        const float4* r4 = (const float4*)(cre + f*64 + ch0);
        const float4* i4 = (const float4*)(cim + f*64 + ch0);
        float rv[16], iv[16];
        #pragma unroll
        for (int u = 0; u < 4; u++) {
            float4 a = r4[u], bb = i4[u];
            rv[4*u] = a.x; rv[4*u+1] = a.y; rv[4*u+2] = a.z; rv[4*u+3] = a.w;
            iv[4*u] = bb.x; iv[4*u+1] = bb.y; iv[4*u+2] = bb.z; iv[4*u+3] = bb.w;
        }
        #pragma unroll
        for (int q = 0; q < 4; q++)
            #pragma unroll
            for (int ch = 0; ch < 16; ch++)
                acc[q][ch] = fmaf(rv[ch], cq[q], fmaf(iv[ch], sq[q], acc[q][ch]));
    }

    #pragma unroll
    for (int q = 0; q < 4; q++) {
        float4* dst = (float4*)(g_xsum + (((size_t)(b*MM + m))*NN + nq[q])*CO + ch0);
        #pragma unroll
        for (int u = 0; u < 4; u++)
            dst[u] = make_float4(acc[q][4*u], acc[q][4*u+1], acc[q][4*u+2], acc[q][4*u+3]);
    }
}

// ---------------- K3X: inverse synthesis along M, accumulate ----------------
__global__ void __launch_bounds__(256) k_invX() {
    extern __shared__ float smf[];
    float* cre = smf;              // [32][64]
    float* cim = smf + 2048;
    float* ct5 = smf + 4096;       // 510
    float* st5 = smf + 4606;       // 510
    int t = threadIdx.x;
    int b = blockIdx.x >> 8, n = blockIdx.x & 255;
    const float inv = 0.04428074428f;
    const float2* Y = g_YfX + ((size_t)b*MODES*NN + n)*CO;
    #pragma unroll
    for (int it = 0; it < 8; it++) {
        int flat = it*256 + t;
        int f = flat >> 6;
        float2 v = Y[(size_t)f*NN*CO + (flat & 63)];
        cre[flat] = v.x * (((f == 0) ? 1.f : 2.f) * inv);
        cim[flat] = v.y * (-2.f * inv);
    }
    ct5[t] = cospif(t * (1.0f/255.0f));
    st5[t] = sinpif(t * (1.0f/255.0f));
    if (t + 256 < 510) {
        ct5[t+256] = cospif((t+256) * (1.0f/255.0f));
        st5[t+256] = sinpif((t+256) * (1.0f/255.0f));
    }
    __syncthreads();

    int mg = t >> 2, cg = t & 3;
    int ch0 = cg * 16;
    int mq[4], idx[4];
    #pragma unroll
    for (int q = 0; q < 4; q++) { mq[q] = mg + 64*q; idx[q] = 0; }

    float acc[4][16];
    #pragma unroll
    for (int q = 0; q < 4; q++)
        #pragma unroll
        for (int ch = 0; ch < 16; ch++) acc[q][ch] = 0.f;

    for (int f = 0; f < MODES; f++) {
        float cq[4], sq[4];
        #pragma unroll
        for (int q = 0; q < 4; q++) {
            cq[q] = ct5[idx[q]]; sq[q] = st5[idx[q]];
            idx[q] += mq[q]; if (idx[q] >= 510) idx[q] -= 510;
        }
        const float4* r4 = (const float4*)(cre + f*64 + ch0);
        const float4* i4 = (const float4*)(cim + f*64 + ch0);
        float rv[16], iv[16];
        #pragma unroll
        for (int u = 0; u < 4; u++) {
            float4 a = r4[u], bb = i4[u];
            rv[4*u] = a.x; rv[4*u+1] = a.y; rv[4*u+2] = a.z; rv[4*u+3] = a.w;
            iv[4*u] = bb.x; iv[4*u+1] = bb.y; iv[4*u+2] = bb.z; iv[4*u+3] = bb.w;
        }
        #pragma unroll
        for (int q = 0; q < 4; q++)
            #pragma unroll
            for (int ch = 0; ch < 16; ch++)
                acc[q][ch] = fmaf(rv[ch], cq[q], fmaf(iv[ch], sq[q], acc[q][ch]));
    }

    #pragma unroll
    for (int q = 0; q < 4; q++) {
        float4* dst = (float4*)(g_xsum + (((size_t)(b*MM + mq[q]))*NN + n)*CO + ch0);
        #pragma unroll
        for (int u = 0; u < 4; u++) {
            float4 v = dst[u];
            v.x += acc[q][4*u]; v.y += acc[q][4*u+1]; v.z += acc[q][4*u+2]; v.w += acc[q][4*u+3];
            dst[u] = v;
        }
    }
}

// ---------------- K4: MLP via mma.sync bf16 split + LayerNorm (unchanged, R4) ----------------
#define SA_HI   0
#define SA_LO   36864
#define SW_BASE 73728
#define S_B1    215040
#define S_B2    216064
#define S_GAM   216320
#define S_BET   216576
#define SM_MLP  216832

__global__ void __launch_bounds__(256) k_mlp_mma(const float* __restrict__ b1,
                                                 const float* __restrict__ b2,
                                                 const float* __restrict__ gamma,
                                                 const float* __restrict__ beta,
                                                 float* __restrict__ out) {
    extern __shared__ __align__(16) unsigned char sm[];
    int t = threadIdx.x;
    int w = t >> 5, l = t & 31;
    int l4 = l >> 2, lq = l & 3;

    {
        const float4* src = (const float4*)g_Wimg;
        float4* dst = (float4*)(sm + SW_BASE);
        for (int i = t; i < W_TOT/16; i += 256) dst[i] = src[i];
    }
    float* b1s = (float*)(sm + S_B1);
    float* b2s = (float*)(sm + S_B2);
    float* gs  = (float*)(sm + S_GAM);
    float* bs  = (float*)(sm + S_BET);
    b1s[t] = b1[t];
    if (t < 64) { b2s[t] = b2[t]; gs[t] = gamma[t]; bs[t] = beta[t]; }

    {
        const float4* xs = (const float4*)(g_xsum + ((size_t)blockIdx.x*256 + t)*64);
        unsigned char* rh = sm + SA_HI + t*144;
        unsigned char* rl = sm + SA_LO + t*144;
        #pragma unroll
        for (int q = 0; q < 16; q++) {
            float4 v = xs[q];
            uint32_t h0, l0, h1, l1;
            cvt_pair(v.x, v.y, h0, l0);
            cvt_pair(v.z, v.w, h1, l1);
            *(uint32_t*)(rh + q*8    ) = h0;
            *(uint32_t*)(rh + q*8 + 4) = h1;
            *(uint32_t*)(rl + q*8    ) = l0;
            *(uint32_t*)(rl + q*8 + 4) = l1;
        }
    }
    __syncthreads();

    float d2[2][8][4];
    #pragma unroll
    for (int mt = 0; mt < 2; mt++)
        #pragma unroll
        for (int j = 0; j < 8; j++)
            #pragma unroll
            for (int q = 0; q < 4; q++) d2[mt][j][q] = 0.f;

    const unsigned char* W1h = sm + SW_BASE + W_W1HI;
    const unsigned char* W1l = sm + SW_BASE + W_W1LO;
    const unsigned char* W2h = sm + SW_BASE + W_W2HI;
    const unsigned char* W2l = sm + SW_BASE + W_W2LO;

    for (int c = 0; c < 4; c++) {
        float h[2][8][4];
        #pragma unroll
        for (int mt = 0; mt < 2; mt++)
            #pragma unroll
            for (int j = 0; j < 8; j++)
                #pragma unroll
                for (int q = 0; q < 4; q++) h[mt][j][q] = 0.f;

        #pragma unroll
        for (int kt = 0; kt < 4; kt++) {
            uint32_t ah[2][4], al[2][4];
            #pragma unroll
            for (int mt = 0; mt < 2; mt++) {
                int row = w*32 + mt*16 + l4;
                int kof = (kt*16 + 2*lq)*2;
                ah[mt][0] = *(const uint32_t*)(sm + SA_HI + row*144 + kof);
                ah[mt][1] = *(const uint32_t*)(sm + SA_HI + (row+8)*144 + kof);
                ah[mt][2] = *(const uint32_t*)(sm + SA_HI + row*144 + kof + 16);
                ah[mt][3] = *(const uint32_t*)(sm + SA_HI + (row+8)*144 + kof + 16);
                al[mt][0] = *(const uint32_t*)(sm + SA_LO + row*144 + kof);
                al[mt][1] = *(const uint32_t*)(sm + SA_LO + (row+8)*144 + kof);
                al[mt][2] = *(const uint32_t*)(sm + SA_LO + row*144 + kof + 16);
                al[mt][3] = *(const uint32_t*)(sm + SA_LO + (row+8)*144 + kof + 16);
            }
            #pragma unroll
            for (int j = 0; j < 8; j++) {
                int n = c*64 + j*8 + l4;
                int kof = (kt*16 + 2*lq)*2;
                uint32_t bh0 = *(const uint32_t*)(W1h + n*144 + kof);
                uint32_t bh1 = *(const uint32_t*)(W1h + n*144 + kof + 16);
                uint32_t bl0 = *(const uint32_t*)(W1l + n*144 + kof);
                uint32_t bl1 = *(const uint32_t*)(W1l + n*144 + kof + 16);
                #pragma unroll
                for (int mt = 0; mt < 2; mt++) {
                    mma_bf16(h[mt][j], ah[mt], bh0, bh1);
                    mma_bf16(h[mt][j], ah[mt], bl0, bl1);
                    mma_bf16(h[mt][j], al[mt], bh0, bh1);
                }
            }
        }

        #pragma unroll
        for (int kt2 = 0; kt2 < 4; kt2++) {
            int j = 2*kt2;
            uint32_t ah2[2][4], al2[2][4];
            #pragma unroll
            for (int mt = 0; mt < 2; mt++) {
                int g0 = c*64 + j*8 + 2*lq;
                float bA = b1s[g0],   bB = b1s[g0+1];
                float bC = b1s[g0+8], bD = b1s[g0+9];
                float v0 = fmaxf(h[mt][j][0] + bA, 0.f);
                float v1 = fmaxf(h[mt][j][1] + bB, 0.f);
                cvt_pair(v0, v1, ah2[mt][0], al2[mt][0]);
                v0 = fmaxf(h[mt][j][2] + bA, 0.f);
                v1 = fmaxf(h[mt][j][3] + bB, 0.f);
                cvt_pair(v0, v1, ah2[mt][1], al2[mt][1]);
                v0 = fmaxf(h[mt][j+1][0] + bC, 0.f);
                v1 = fmaxf(h[mt][j+1][1] + bD, 0.f);
                cvt_pair(v0, v1, ah2[mt][2], al2[mt][2]);
                v0 = fmaxf(h[mt][j+1][2] + bC, 0.f);
                v1 = fmaxf(h[mt][j+1][3] + bD, 0.f);
                cvt_pair(v0, v1, ah2[mt][3], al2[mt][3]);
            }
            int k0 = c*64 + kt2*16;
            #pragma unroll
            for (int j2 = 0; j2 < 8; j2++) {
                int n = j2*8 + l4;
                int kof = (k0 + 2*lq)*2;
                uint32_t bh0 = *(const uint32_t*)(W2h + n*528 + kof);
                uint32_t bh1 = *(const uint32_t*)(W2h + n*528 + kof + 16);
                uint32_t bl0 = *(const uint32_t*)(W2l + n*528 + kof);
                uint32_t bl1 = *(const uint32_t*)(W2l + n*528 + kof + 16);
                #pragma unroll
                for (int mt = 0; mt < 2; mt++) {
                    mma_bf16(d2[mt][j2], ah2[mt], bh0, bh1);
                    mma_bf16(d2[mt][j2], ah2[mt], bl0, bl1);
                    mma_bf16(d2[mt][j2], al2[mt], bh0, bh1);
                }
            }
        }
    }

    #pragma unroll
    for (int mt = 0; mt < 2; mt++) {
        #pragma unroll
        for (int rh = 0; rh < 2; rh++) {
            float vals[16];
            #pragma unroll
            for (int j2 = 0; j2 < 8; j2++) {
                int col = j2*8 + 2*lq;
                vals[2*j2  ] = d2[mt][j2][2*rh  ] + b2s[col];
                vals[2*j2+1] = d2[mt][j2][2*rh+1] + b2s[col+1];
            }
            float s = 0.f;
            #pragma unroll
            for (int q = 0; q < 16; q++) s += vals[q];
            s += __shfl_xor_sync(0xffffffffu, s, 1);
            s += __shfl_xor_sync(0xffffffffu, s, 2);
            float mu = s * (1.f/64.f);
            float v = 0.f;
            #pragma unroll
            for (int q = 0; q < 16; q++) { float d = vals[q] - mu; v = fmaf(d, d, v); }
            v += __shfl_xor_sync(0xffffffffu, v, 1);
            v += __shfl_xor_sync(0xffffffffu, v, 2);
            float rinv = rsqrtf(v * (1.f/64.f) + 1e-5f);
            size_t row = (size_t)blockIdx.x*256 + w*32 + mt*16 + rh*8 + l4;
            #pragma unroll
            for (int j2 = 0; j2 < 8; j2++) {
                int col = j2*8 + 2*lq;
                float2 r;
                r.x = (vals[2*j2  ] - mu) * rinv * gs[col  ] + bs[col  ];
                r.y = (vals[2*j2+1] - mu) * rinv * gs[col+1] + bs[col+1];
                *(float2*)(out + row*64 + col) = r;
            }
        }
    }
}

// ---------------- launcher ----------------
extern "C" void kernel_launch(void* const* d_in, const int* in_sizes, int n_in,
                              void* d_out, int out_size) {
    (void)in_sizes; (void)n_in; (void)out_size;
    const float* x     = (const float*)d_in[0];
    const float* att   = (const float*)d_in[1];
    const float* fwy   = (const float*)d_in[2];
    const float* fwx   = (const float*)d_in[3];
    const float* w1    = (const float*)d_in[4];
    const float* b1    = (const float*)d_in[5];
    const float* w2    = (const float*)d_in[6];
    const float* b2    = (const float*)d_in[7];
    const float* gamma = (const float*)d_in[8];
    const float* beta  = (const float*)d_in[9];
    float* out = (float*)d_out;

    const int SM_FWDY = 17152 * 4;          // 68608
    const int SM_FWDX = 17024 * 4;          // 68096
    const int SM_INVY = 4608 * 4;           // 18432
    const int SM_INVX = 5116 * 4;           // 20464

    cudaFuncSetAttribute(k_fwdY,    cudaFuncAttributeMaxDynamicSharedMemorySize, SM_FWDY);
    cudaFuncSetAttribute(k_fwdX,    cudaFuncAttributeMaxDynamicSharedMemorySize, SM_FWDX);
    cudaFuncSetAttribute(k_mix_mma, cudaFuncAttributeMaxDynamicSharedMemorySize, MX_TOT);
    cudaFuncSetAttribute(k_mlp_mma, cudaFuncAttributeMaxDynamicSharedMemorySize, SM_MLP);

    k_weights<<<(BATCH*MODES*CI*CO)/256, 256>>>(att, fwy, fwx);
    k_wprep<<<128, 256>>>(w1, w2);
    k_fwdY<<<BATCH*MM, 256, SM_FWDY>>>(x);
    k_fwdX<<<BATCH*NN, 256, SM_FWDX>>>(x);
    k_mix_mma<<<2*BATCH*MODES, 256, MX_TOT>>>();
    k_invY<<<BATCH*MM, 256, SM_INVY>>>();
    k_invX<<<BATCH*NN, 256, SM_INVX>>>();
    k_mlp_mma<<<(BATCH*MM*NN)/256, 256, SM_MLP>>>(b1, b2, gamma, beta, out);
}

// round 6
// speedup vs baseline: 2.4861x; 1.0569x over previous
#include <cuda_runtime.h>
#include <cuda_bf16.h>
#include <cstdint>

#define BATCH 8
#define MM 256
#define NN 256
#define CI 64
#define CO 64
#define KK 4
#define MODES 32

typedef unsigned long long u64;

// ---------------- scratch ----------------
__device__ float2 g_wy [BATCH*MODES*CI*CO];
__device__ float2 g_wx [BATCH*MODES*CI*CO];
__device__ float2 g_XfY[BATCH*MODES*MM*CI];
__device__ float2 g_XfX[BATCH*MODES*NN*CI];
__device__ float2 g_YfY[BATCH*MODES*MM*CO];
__device__ float2 g_YfX[BATCH*MODES*NN*CO];
__device__ float  g_xsum [(size_t)BATCH*MM*NN*CO];
__device__ float  g_xsum2[(size_t)BATCH*MM*NN*CO];

// MLP weight image
#define W_W1HI 0
#define W_W1LO 36864
#define W_W2HI 73728
#define W_W2LO 107520
#define W_TOT  141312
__device__ __align__(16) unsigned char g_Wimg[W_TOT];

// transform tables (split bf16, smem-image layout)
// fwd: 64 rows x 256 k, row stride 520 B; hi [0,33280), lo [33280,66560)
#define T_ST   520
#define T_LOB  33280
#define T_TOT  66560
__device__ __align__(16) unsigned char g_TY[T_TOT];
__device__ __align__(16) unsigned char g_TX[T_TOT];
// inv: 256 rows x 64 k, row stride 136 B; hi [0,34816), lo [34816,69632)
#define S_ST   136
#define S_LOB  34816
#define S_TOT  69632
__device__ __align__(16) unsigned char g_SY[S_TOT];
__device__ __align__(16) unsigned char g_SX[S_TOT];

// ---------------- bf16 helpers ----------------
__device__ __forceinline__ void cvt_pair(float v0, float v1, uint32_t& hi, uint32_t& lo) {
    __nv_bfloat16 h0 = __float2bfloat16(v0), h1 = __float2bfloat16(v1);
    float r0 = v0 - __bfloat162float(h0);
    float r1 = v1 - __bfloat162float(h1);
    hi = (uint32_t)__bfloat16_as_ushort(h0) | ((uint32_t)__bfloat16_as_ushort(h1) << 16);
    lo = (uint32_t)__bfloat16_as_ushort(__float2bfloat16(r0))
       | ((uint32_t)__bfloat16_as_ushort(__float2bfloat16(r1)) << 16);
}
__device__ __forceinline__ void mma_bf16(float* d, const uint32_t* a, uint32_t b0, uint32_t b1) {
    asm volatile(
        "mma.sync.aligned.m16n8k16.row.col.f32.bf16.bf16.f32 "
        "{%0,%1,%2,%3},{%4,%5,%6,%7},{%8,%9},{%0,%1,%2,%3};"
        : "+f"(d[0]), "+f"(d[1]), "+f"(d[2]), "+f"(d[3])
        : "r"(a[0]), "r"(a[1]), "r"(a[2]), "r"(a[3]), "r"(b0), "r"(b1));
}
__device__ __forceinline__ void wr_split(unsigned char* phi, unsigned char* plo, float v) {
    __nv_bfloat16 h = __float2bfloat16(v);
    float r = v - __bfloat162float(h);
    *(unsigned short*)phi = __bfloat16_as_ushort(h);
    *(unsigned short*)plo = __bfloat16_as_ushort(__float2bfloat16(r));
}

// ---------------- K0: spectral weights ----------------
__global__ void k_weights(const float* __restrict__ att,
                          const float* __restrict__ fwy,
                          const float* __restrict__ fwx) {
    int gid = blockIdx.x * 256 + threadIdx.x;
    int o = gid & 63, i = (gid >> 6) & 63, f = (gid >> 12) & 31, b = gid >> 17;
    float a0 = att[b*KK+0], a1 = att[b*KK+1], a2 = att[b*KK+2], a3 = att[b*KK+3];
    const int ks = CI*CO*MODES*2;
    int base = ((i*CO + o)*MODES + f)*2;
    float yr, yi, xr, xi;
    yr = a0*fwy[base   ] + a1*fwy[base+ks   ] + a2*fwy[base+2*ks  ] + a3*fwy[base+3*ks  ];
    yi = a0*fwy[base+1 ] + a1*fwy[base+ks+1 ] + a2*fwy[base+2*ks+1] + a3*fwy[base+3*ks+1];
    xr = a0*fwx[base   ] + a1*fwx[base+ks   ] + a2*fwx[base+2*ks  ] + a3*fwx[base+3*ks  ];
    xi = a0*fwx[base+1 ] + a1*fwx[base+ks+1 ] + a2*fwx[base+2*ks+1] + a3*fwx[base+3*ks+1];
    g_wy[gid] = make_float2(yr, yi);
    g_wx[gid] = make_float2(xr, xi);
}

// ---------------- K0b: MLP weight image ----------------
__global__ void k_wprep(const float* __restrict__ w1, const float* __restrict__ w2) {
    int gid = blockIdx.x * 256 + threadIdx.x;
    if (gid < 16384) {
        int i = gid >> 8, j = gid & 255;
        uint32_t off = (uint32_t)j*144 + (uint32_t)i*2;
        wr_split(g_Wimg + W_W1HI + off, g_Wimg + W_W1LO + off, w1[gid]);
    } else {
        int idx = gid - 16384;
        int j = idx >> 6, o = idx & 63;
        uint32_t off = (uint32_t)o*528 + (uint32_t)j*2;
        wr_split(g_Wimg + W_W2HI + off, g_Wimg + W_W2LO + off, w2[idx]);
    }
}

// ---------------- K0c: transform tables ----------------
__global__ void k_tprep() {
    int gid = blockIdx.x * 256 + threadIdx.x;   // 65536
    int sel = gid >> 14;
    int idx = gid & 16383;
    const float inv = 0.04428074428f;   // 1/sqrt(510)
    if (sel == 0) {                      // TY: rows 64, k 256
        int r = idx >> 8, k = idx & 255;
        int f = r >> 1;
        float ang = (float)((f*k) & 255) * (1.0f/128.0f);
        float v = (r & 1) ? -0.0625f*sinpif(ang) : 0.0625f*cospif(ang);
        uint32_t off = (uint32_t)r*T_ST + (uint32_t)k*2;
        wr_split(g_TY + off, g_TY + T_LOB + off, v);
    } else if (sel == 1) {               // TX
        int r = idx >> 8, k = idx & 255;
        int f = r >> 1;
        float v;
        if (r & 1) v = -2.0f*inv*sinpif((float)((f*k) % 510) * (1.0f/255.0f));
        else       v = (k == 0) ? inv : ((k == 255) ? ((f & 1) ? -inv : inv) : 0.0f);
        uint32_t off = (uint32_t)r*T_ST + (uint32_t)k*2;
        wr_split(g_TX + off, g_TX + T_LOB + off, v);
    } else if (sel == 2) {               // SY: rows 256, k 64
        int r = idx >> 6, k = idx & 63;
        int f = k >> 1;
        float ang = (float)((f*r) & 255) * (1.0f/128.0f);
        float v = (k & 1) ? -0.125f*sinpif(ang)
                          : ((f == 0) ? 0.0625f : 0.125f)*cospif(ang);
        uint32_t off = (uint32_t)r*S_ST + (uint32_t)k*2;
        wr_split(g_SY + off, g_SY + S_LOB + off, v);
    } else {                             // SX
        int r = idx >> 6, k = idx & 63;
        int f = k >> 1;
        float ang = (float)((f*r) % 510) * (1.0f/255.0f);
        float v = (k & 1) ? -2.0f*inv*sinpif(ang)
                          : ((f == 0) ? inv : 2.0f*inv)*cospif(ang);
        uint32_t off = (uint32_t)r*S_ST + (uint32_t)k*2;
        wr_split(g_SX + off, g_SX + S_LOB + off, v);
    }
}

// ---------------- K1: forward transforms via mma.sync ----------------
// grid 4096: branch = bi>>11 (0=Y along n, 1=X along m); block per (b, m|n)
// smem: Tsm [0,66560), Bsm [66560, 133120)
#define FW_B   66560
#define FW_TOT 133120
__global__ void __launch_bounds__(256) k_fwd_mma(const float* __restrict__ x) {
    extern __shared__ __align__(16) unsigned char sm[];
    int t = threadIdx.x, w = t >> 5, l = t & 31, l4 = l >> 2, lq = l & 3;
    int bi = blockIdx.x;
    int branch = bi >> 11;
    int bm = bi & 2047;
    int b = bm >> 8, mn = bm & 255;

    // copy table
    {
        const float4* src = (const float4*)(branch ? g_TX : g_TY);
        float4* dst = (float4*)sm;
        for (int i = t; i < T_TOT/16; i += 256) dst[i] = src[i];
    }
    // stage B = X^T [ch][k], split, pairs of k packed per u32
    {
        #pragma unroll
        for (int it = 0; it < 8; it++) {
            int flat = it*256 + t;              // 2048
            int kp = flat >> 4, c4 = flat & 15; // k pair, ch quad
            const float* p0;
            size_t stride1;
            if (branch == 0) {
                p0 = x + ((size_t)(b*256 + mn))*16384 + (size_t)(2*kp)*64 + c4*4;
                stride1 = 64;
            } else {
                p0 = x + (((size_t)(b*256 + 2*kp))*256 + mn)*64 + c4*4;
                stride1 = 16384;
            }
            float4 r0 = *(const float4*)p0;
            float4 r1 = *(const float4*)(p0 + stride1);
            float a0[4] = {r0.x, r0.y, r0.z, r0.w};
            float a1[4] = {r1.x, r1.y, r1.z, r1.w};
            #pragma unroll
            for (int j = 0; j < 4; j++) {
                uint32_t hi, lo;
                cvt_pair(a0[j], a1[j], hi, lo);
                uint32_t off = (uint32_t)(4*c4 + j)*T_ST + (uint32_t)kp*4;
                *(uint32_t*)(sm + FW_B + off)         = hi;
                *(uint32_t*)(sm + FW_B + T_LOB + off) = lo;
            }
        }
    }
    __syncthreads();

    // MMA: C[64 rows f/reim][64 ch] ; warp: mt = w&3 (m16 tile), nh = w>>2 (32 cols)
    int mt = w & 3, nh = w >> 2;
    float c[4][4];
    #pragma unroll
    for (int j = 0; j < 4; j++)
        #pragma unroll
        for (int q = 0; q < 4; q++) c[j][q] = 0.f;

    const unsigned char* Th = sm;
    const unsigned char* Tl = sm + T_LOB;
    const unsigned char* Bh = sm + FW_B;
    const unsigned char* Bl = sm + FW_B + T_LOB;

    #pragma unroll
    for (int kk = 0; kk < 16; kk++) {
        int kof = kk*32 + lq*4;
        int r0 = mt*16 + l4;
        uint32_t ah[4], al[4];
        ah[0] = *(const uint32_t*)(Th + r0*T_ST + kof);
        ah[1] = *(const uint32_t*)(Th + (r0+8)*T_ST + kof);
        ah[2] = *(const uint32_t*)(Th + r0*T_ST + kof + 16);
        ah[3] = *(const uint32_t*)(Th + (r0+8)*T_ST + kof + 16);
        al[0] = *(const uint32_t*)(Tl + r0*T_ST + kof);
        al[1] = *(const uint32_t*)(Tl + (r0+8)*T_ST + kof);
        al[2] = *(const uint32_t*)(Tl + r0*T_ST + kof + 16);
        al[3] = *(const uint32_t*)(Tl + (r0+8)*T_ST + kof + 16);
        #pragma unroll
        for (int j = 0; j < 4; j++) {
            int ncol = nh*32 + j*8 + l4;
            uint32_t bh0 = *(const uint32_t*)(Bh + ncol*T_ST + kof);
            uint32_t bh1 = *(const uint32_t*)(Bh + ncol*T_ST + kof + 16);
            uint32_t bl0 = *(const uint32_t*)(Bl + ncol*T_ST + kof);
            uint32_t bl1 = *(const uint32_t*)(Bl + ncol*T_ST + kof + 16);
            mma_bf16(c[j], ah, bh0, bh1);
            mma_bf16(c[j], ah, bl0, bl1);
            mma_bf16(c[j], al, bh0, bh1);
        }
    }

    // scatter to g_Xf*: row r -> (f=r>>1, p=r&1); col -> channel
    float* outb = (float*)(branch ? g_XfX : g_XfY);
    #pragma unroll
    for (int j = 0; j < 4; j++) {
        int ch = nh*32 + j*8 + 2*lq;
        int r0 = mt*16 + l4, r1 = r0 + 8;
        size_t base0 = ((size_t)(b*32 + (r0 >> 1))*256 + mn)*128 + ch*2 + (r0 & 1);
        size_t base1 = ((size_t)(b*32 + (r1 >> 1))*256 + mn)*128 + ch*2 + (r1 & 1);
        outb[base0]     = c[j][0];
        outb[base0 + 2] = c[j][1];
        outb[base1]     = c[j][2];
        outb[base1 + 2] = c[j][3];
    }
}

// ---------------- K2: complex GEMM via mma.sync (unchanged, proven) ----------------
#define MX_AHI 0
#define MX_ALO 69632
#define MX_WHI 139264
#define MX_WLO 174080
#define MX_TOT 208896

__global__ void __launch_bounds__(256) k_mix_mma() {
    extern __shared__ __align__(16) unsigned char sm[];
    int t = threadIdx.x, w = t >> 5, l = t & 31, l4 = l >> 2, lq = l & 3;
    int z = blockIdx.x, branch = z >> 8, bf = z & 255;
    const float2* A = (branch ? g_XfX : g_XfY) + (size_t)bf*MM*CI;
    const float2* W = (branch ? g_wx  : g_wy ) + (size_t)bf*CI*CO;
    float2*       C = (branch ? g_YfX : g_YfY) + (size_t)bf*MM*CO;

    {
        const float4* Af = (const float4*)A;
        #pragma unroll
        for (int it = 0; it < 32; it++) {
            int ft = it*256 + t;
            int row = ft >> 5, c4 = ft & 31;
            float4 v = Af[ft];
            uint32_t h01, l01, h23, l23;
            cvt_pair(v.x, v.y, h01, l01);
            cvt_pair(v.z, v.w, h23, l23);
            *(uint2*)(sm + MX_AHI + row*272 + c4*8) = make_uint2(h01, h23);
            *(uint2*)(sm + MX_ALO + row*272 + c4*8) = make_uint2(l01, l23);
        }
    }
    {
        #pragma unroll
        for (int it = 0; it < 16; it++) {
            int flat = it*256 + t;
            int i = flat >> 6, o = flat & 63;
            float2 wv = W[flat];
            uint32_t ha, la, hb, lb;
            cvt_pair(wv.x, -wv.y, ha, la);
            cvt_pair(wv.y,  wv.x, hb, lb);
            *(uint32_t*)(sm + MX_WHI + (2*o  )*272 + i*4) = ha;
            *(uint32_t*)(sm + MX_WHI + (2*o+1)*272 + i*4) = hb;
            *(uint32_t*)(sm + MX_WLO + (2*o  )*272 + i*4) = la;
            *(uint32_t*)(sm + MX_WLO + (2*o+1)*272 + i*4) = lb;
        }
    }
    __syncthreads();

    float acc[2][16][4];
    #pragma unroll
    for (int mt = 0; mt < 2; mt++)
        #pragma unroll
        for (int j2 = 0; j2 < 16; j2++)
            #pragma unroll
            for (int q = 0; q < 4; q++) acc[mt][j2][q] = 0.f;

    int m0 = w*32;
    #pragma unroll
    for (int kt = 0; kt < 8; kt++) {
        int kof = kt*32 + lq*4;
        uint32_t ah[2][4], al[2][4];
        #pragma unroll
        for (int mt = 0; mt < 2; mt++) {
            int row = m0 + mt*16 + l4;
            ah[mt][0] = *(const uint32_t*)(sm + MX_AHI + row*272 + kof);
            ah[mt][1] = *(const uint32_t*)(sm + MX_AHI + (row+8)*272 + kof);
            ah[mt][2] = *(const uint32_t*)(sm + MX_AHI + row*272 + kof + 16);
            ah[mt][3] = *(const uint32_t*)(sm + MX_AHI + (row+8)*272 + kof + 16);
            al[mt][0] = *(const uint32_t*)(sm + MX_ALO + row*272 + kof);
            al[mt][1] = *(const uint32_t*)(sm + MX_ALO + (row+8)*272 + kof);
            al[mt][2] = *(const uint32_t*)(sm + MX_ALO + row*272 + kof + 16);
            al[mt][3] = *(const uint32_t*)(sm + MX_ALO + (row+8)*272 + kof + 16);
        }
        #pragma unroll
        for (int j2 = 0; j2 < 16; j2++) {
            int nrow = j2*8 + l4;
            uint32_t bh0 = *(const uint32_t*)(sm + MX_WHI + nrow*272 + kof);
            uint32_t bh1 = *(const uint32_t*)(sm + MX_WHI + nrow*272 + kof + 16);
            uint32_t bl0 = *(const uint32_t*)(sm + MX_WLO + nrow*272 + kof);
            uint32_t bl1 = *(const uint32_t*)(sm + MX_WLO + nrow*272 + kof + 16);
            #pragma unroll
            for (int mt = 0; mt < 2; mt++) {
                mma_bf16(acc[mt][j2], ah[mt], bh0, bh1);
                mma_bf16(acc[mt][j2], ah[mt], bl0, bl1);
                mma_bf16(acc[mt][j2], al[mt], bh0, bh1);
            }
        }
    }

    float* Cf = (float*)C;
    #pragma unroll
    for (int mt = 0; mt < 2; mt++) {
        #pragma unroll
        for (int j2 = 0; j2 < 16; j2++) {
            int row = m0 + mt*16 + l4;
            int col = j2*8 + 2*lq;
            *(float2*)(Cf + (size_t)row*128 + col)     = make_float2(acc[mt][j2][0], acc[mt][j2][1]);
            *(float2*)(Cf + (size_t)(row+8)*128 + col) = make_float2(acc[mt][j2][2], acc[mt][j2][3]);
        }
    }
}

// ---------------- K3: inverse transforms via mma.sync ----------------
// grid 4096: branch = bi>>11 (0: Y->g_xsum, 1: X->g_xsum2)
// smem: Ssm [0,69632), Bsm [69632, 87040)
#define IV_B   69632
#define IV_TOT 87040
#define IV_BLO 8704      // Bsm lo offset within Bsm region (64*136)
__global__ void __launch_bounds__(256) k_inv_mma() {
    extern __shared__ __align__(16) unsigned char sm[];
    int t = threadIdx.x, w = t >> 5, l = t & 31, l4 = l >> 2, lq = l & 3;
    int bi = blockIdx.x;
    int branch = bi >> 11;
    int bm = bi & 2047;
    int b = bm >> 8, mn = bm & 255;

    {
        const float4* src = (const float4*)(branch ? g_SX : g_SY);
        float4* dst = (float4*)sm;
        for (int i = t; i < S_TOT/16; i += 256) dst[i] = src[i];
    }
    // stage B: B[ch][k=2f|2f+1] = (re,im) of Y[f][ch]
    {
        const float2* Y = (branch ? g_YfX : g_YfY);
        #pragma unroll
        for (int it = 0; it < 8; it++) {
            int flat = it*256 + t;           // 2048 = 32f x 64ch
            int f = flat >> 6, ch = flat & 63;
            float2 v = Y[((size_t)(b*32 + f)*256 + mn)*64 + ch];
            uint32_t hi, lo;
            cvt_pair(v.x, v.y, hi, lo);
            uint32_t off = (uint32_t)ch*S_ST + (uint32_t)f*4;
            *(uint32_t*)(sm + IV_B + off)          = hi;
            *(uint32_t*)(sm + IV_B + IV_BLO + off) = lo;
        }
    }
    __syncthreads();

    // MMA: C[256 rows][64 ch]; warp w handles m-tiles {w, w+8}
    float c[2][8][4];
    #pragma unroll
    for (int mt = 0; mt < 2; mt++)
        #pragma unroll
        for (int j = 0; j < 8; j++)
            #pragma unroll
            for (int q = 0; q < 4; q++) c[mt][j][q] = 0.f;

    const unsigned char* Sh = sm;
    const unsigned char* Sl = sm + S_LOB;
    const unsigned char* Bh = sm + IV_B;
    const unsigned char* Bl = sm + IV_B + IV_BLO;

    #pragma unroll
    for (int kk = 0; kk < 4; kk++) {
        int kof = kk*32 + lq*4;
        uint32_t ah[2][4], al[2][4];
        #pragma unroll
        for (int mt = 0; mt < 2; mt++) {
            int r0 = (w + mt*8)*16 + l4;
            ah[mt][0] = *(const uint32_t*)(Sh + r0*S_ST + kof);
            ah[mt][1] = *(const uint32_t*)(Sh + (r0+8)*S_ST + kof);
            ah[mt][2] = *(const uint32_t*)(Sh + r0*S_ST + kof + 16);
            ah[mt][3] = *(const uint32_t*)(Sh + (r0+8)*S_ST + kof + 16);
            al[mt][0] = *(const uint32_t*)(Sl + r0*S_ST + kof);
            al[mt][1] = *(const uint32_t*)(Sl + (r0+8)*S_ST + kof);
            al[mt][2] = *(const uint32_t*)(Sl + r0*S_ST + kof + 16);
            al[mt][3] = *(const uint32_t*)(Sl + (r0+8)*S_ST + kof + 16);
        }
        #pragma unroll
        for (int j = 0; j < 8; j++) {
            int ncol = j*8 + l4;
            uint32_t bh0 = *(const uint32_t*)(Bh + ncol*S_ST + kof);
            uint32_t bh1 = *(const uint32_t*)(Bh + ncol*S_ST + kof + 16);
            uint32_t bl0 = *(const uint32_t*)(Bl + ncol*S_ST + kof);
            uint32_t bl1 = *(const uint32_t*)(Bl + ncol*S_ST + kof + 16);
            #pragma unroll
            for (int mt = 0; mt < 2; mt++) {
                mma_bf16(c[mt][j], ah[mt], bh0, bh1);
                mma_bf16(c[mt][j], ah[mt], bl0, bl1);
                mma_bf16(c[mt][j], al[mt], bh0, bh1);
            }
        }
    }

    // write out
    float* outb = branch ? g_xsum2 : g_xsum;
    #pragma unroll
    for (int mt = 0; mt < 2; mt++) {
        #pragma unroll
        for (int j = 0; j < 8; j++) {
            int col = j*8 + 2*lq;
            int r0 = (w + mt*8)*16 + l4, r1 = r0 + 8;
            size_t a0, a1;
            if (branch == 0) {
                a0 = (((size_t)(b*256 + mn))*256 + r0)*64 + col;
                a1 = (((size_t)(b*256 + mn))*256 + r1)*64 + col;
            } else {
                a0 = (((size_t)(b*256 + r0))*256 + mn)*64 + col;
                a1 = (((size_t)(b*256 + r1))*256 + mn)*64 + col;
            }
            *(float2*)(outb + a0) = make_float2(c[mt][j][0], c[mt][j][1]);
            *(float2*)(outb + a1) = make_float2(c[mt][j][2], c[mt][j][3]);
        }
    }
}

// ---------------- K4: MLP via mma.sync + LayerNorm (sums two xsum buffers) ----------------
#define SA_HI   0
#define SA_LO   36864
#define SW_BASE 73728
#define S_B1    215040
#define S_B2    216064
#define S_GAM   216320
#define S_BET   216576
#define SM_MLP  216832

__global__ void __launch_bounds__(256) k_mlp_mma(const float* __restrict__ b1,
                                                 const float* __restrict__ b2,
                                                 const float* __restrict__ gamma,
                                                 const float* __restrict__ beta,
                                                 float* __restrict__ out) {
    extern __shared__ __align__(16) unsigned char sm[];
    int t = threadIdx.x;
    int w = t >> 5, l = t & 31;
    int l4 = l >> 2, lq = l & 3;

    {
        const float4* src = (const float4*)g_Wimg;
        float4* dst = (float4*)(sm + SW_BASE);
        for (int i = t; i < W_TOT/16; i += 256) dst[i] = src[i];
    }
    float* b1s = (float*)(sm + S_B1);
    float* b2s = (float*)(sm + S_B2);
    float* gs  = (float*)(sm + S_GAM);
    float* bs  = (float*)(sm + S_BET);
    b1s[t] = b1[t];
    if (t < 64) { b2s[t] = b2[t]; gs[t] = gamma[t]; bs[t] = beta[t]; }

    {
        const float4* xs  = (const float4*)(g_xsum  + ((size_t)blockIdx.x*256 + t)*64);
        const float4* xs2 = (const float4*)(g_xsum2 + ((size_t)blockIdx.x*256 + t)*64);
        unsigned char* rh = sm + SA_HI + t*144;
        unsigned char* rl = sm + SA_LO + t*144;
        #pragma unroll
        for (int q = 0; q < 16; q++) {
            float4 v = xs[q], v2 = xs2[q];
            v.x += v2.x; v.y += v2.y; v.z += v2.z; v.w += v2.w;
            uint32_t h0, l0, h1, l1;
            cvt_pair(v.x, v.y, h0, l0);
            cvt_pair(v.z, v.w, h1, l1);
            *(uint32_t*)(rh + q*8    ) = h0;
            *(uint32_t*)(rh + q*8 + 4) = h1;
            *(uint32_t*)(rl + q*8    ) = l0;
            *(uint32_t*)(rl + q*8 + 4) = l1;
        }
    }
    __syncthreads();

    float d2[2][8][4];
    #pragma unroll
    for (int mt = 0; mt < 2; mt++)
        #pragma unroll
        for (int j = 0; j < 8; j++)
            #pragma unroll
            for (int q = 0; q < 4; q++) d2[mt][j][q] = 0.f;

    const unsigned char* W1h = sm + SW_BASE + W_W1HI;
    const unsigned char* W1l = sm + SW_BASE + W_W1LO;
    const unsigned char* W2h = sm + SW_BASE + W_W2HI;
    const unsigned char* W2l = sm + SW_BASE + W_W2LO;

    for (int c = 0; c < 4; c++) {
        float h[2][8][4];
        #pragma unroll
        for (int mt = 0; mt < 2; mt++)
            #pragma unroll
            for (int j = 0; j < 8; j++)
                #pragma unroll
                for (int q = 0; q < 4; q++) h[mt][j][q] = 0.f;

        #pragma unroll
        for (int kt = 0; kt < 4; kt++) {
            uint32_t ah[2][4], al[2][4];
            #pragma unroll
            for (int mt = 0; mt < 2; mt++) {
                int row = w*32 + mt*16 + l4;
                int kof = (kt*16 + 2*lq)*2;
                ah[mt][0] = *(const uint32_t*)(sm + SA_HI + row*144 + kof);
                ah[mt][1] = *(const uint32_t*)(sm + SA_HI + (row+8)*144 + kof);
                ah[mt][2] = *(const uint32_t*)(sm + SA_HI + row*144 + kof + 16);
                ah[mt][3] = *(const uint32_t*)(sm + SA_HI + (row+8)*144 + kof + 16);
                al[mt][0] = *(const uint32_t*)(sm + SA_LO + row*144 + kof);
                al[mt][1] = *(const uint32_t*)(sm + SA_LO + (row+8)*144 + kof);
                al[mt][2] = *(const uint32_t*)(sm + SA_LO + row*144 + kof + 16);
                al[mt][3] = *(const uint32_t*)(sm + SA_LO + (row+8)*144 + kof + 16);
            }
            #pragma unroll
            for (int j = 0; j < 8; j++) {
                int n = c*64 + j*8 + l4;
                int kof = (kt*16 + 2*lq)*2;
                uint32_t bh0 = *(const uint32_t*)(W1h + n*144 + kof);
                uint32_t bh1 = *(const uint32_t*)(W1h + n*144 + kof + 16);
                uint32_t bl0 = *(const uint32_t*)(W1l + n*144 + kof);
                uint32_t bl1 = *(const uint32_t*)(W1l + n*144 + kof + 16);
                #pragma unroll
                for (int mt = 0; mt < 2; mt++) {
                    mma_bf16(h[mt][j], ah[mt], bh0, bh1);
                    mma_bf16(h[mt][j], ah[mt], bl0, bl1);
                    mma_bf16(h[mt][j], al[mt], bh0, bh1);
                }
            }
        }

        #pragma unroll
        for (int kt2 = 0; kt2 < 4; kt2++) {
            int j = 2*kt2;
            uint32_t ah2[2][4], al2[2][4];
            #pragma unroll
            for (int mt = 0; mt < 2; mt++) {
                int g0 = c*64 + j*8 + 2*lq;
                float bA = b1s[g0],   bB = b1s[g0+1];
                float bC = b1s[g0+8], bD = b1s[g0+9];
                float v0 = fmaxf(h[mt][j][0] + bA, 0.f);
                float v1 = fmaxf(h[mt][j][1] + bB, 0.f);
                cvt_pair(v0, v1, ah2[mt][0], al2[mt][0]);
                v0 = fmaxf(h[mt][j][2] + bA, 0.f);
                v1 = fmaxf(h[mt][j][3] + bB, 0.f);
                cvt_pair(v0, v1, ah2[mt][1], al2[mt][1]);
                v0 = fmaxf(h[mt][j+1][0] + bC, 0.f);
                v1 = fmaxf(h[mt][j+1][1] + bD, 0.f);
                cvt_pair(v0, v1, ah2[mt][2], al2[mt][2]);
                v0 = fmaxf(h[mt][j+1][2] + bC, 0.f);
                v1 = fmaxf(h[mt][j+1][3] + bD, 0.f);
                cvt_pair(v0, v1, ah2[mt][3], al2[mt][3]);
            }
            int k0 = c*64 + kt2*16;
            #pragma unroll
            for (int j2 = 0; j2 < 8; j2++) {
                int n = j2*8 + l4;
                int kof = (k0 + 2*lq)*2;
                uint32_t bh0 = *(const uint32_t*)(W2h + n*528 + kof);
                uint32_t bh1 = *(const uint32_t*)(W2h + n*528 + kof + 16);
                uint32_t bl0 = *(const uint32_t*)(W2l + n*528 + kof);
                uint32_t bl1 = *(const uint32_t*)(W2l + n*528 + kof + 16);
                #pragma unroll
                for (int mt = 0; mt < 2; mt++) {
                    mma_bf16(d2[mt][j2], ah2[mt], bh0, bh1);
                    mma_bf16(d2[mt][j2], ah2[mt], bl0, bl1);
                    mma_bf16(d2[mt][j2], al2[mt], bh0, bh1);
                }
            }
        }
    }

    #pragma unroll
    for (int mt = 0; mt < 2; mt++) {
        #pragma unroll
        for (int rh = 0; rh < 2; rh++) {
            float vals[16];
            #pragma unroll
            for (int j2 = 0; j2 < 8; j2++) {
                int col = j2*8 + 2*lq;
                vals[2*j2  ] = d2[mt][j2][2*rh  ] + b2s[col];
                vals[2*j2+1] = d2[mt][j2][2*rh+1] + b2s[col+1];
            }
            float s = 0.f;
            #pragma unroll
            for (int q = 0; q < 16; q++) s += vals[q];
            s += __shfl_xor_sync(0xffffffffu, s, 1);
            s += __shfl_xor_sync(0xffffffffu, s, 2);
            float mu = s * (1.f/64.f);
            float v = 0.f;
            #pragma unroll
            for (int q = 0; q < 16; q++) { float d = vals[q] - mu; v = fmaf(d, d, v); }
            v += __shfl_xor_sync(0xffffffffu, v, 1);
            v += __shfl_xor_sync(0xffffffffu, v, 2);
            float rinv = rsqrtf(v * (1.f/64.f) + 1e-5f);
            size_t row = (size_t)blockIdx.x*256 + w*32 + mt*16 + rh*8 + l4;
            #pragma unroll
            for (int j2 = 0; j2 < 8; j2++) {
                int col = j2*8 + 2*lq;
                float2 r;
                r.x = (vals[2*j2  ] - mu) * rinv * gs[col  ] + bs[col  ];
                r.y = (vals[2*j2+1] - mu) * rinv * gs[col+1] + bs[col+1];
                *(float2*)(out + row*64 + col) = r;
            }
        }
    }
}

// ---------------- launcher ----------------
extern "C" void kernel_launch(void* const* d_in, const int* in_sizes, int n_in,
                              void* d_out, int out_size) {
    (void)in_sizes; (void)n_in; (void)out_size;
    const float* x     = (const float*)d_in[0];
    const float* att   = (const float*)d_in[1];
    const float* fwy   = (const float*)d_in[2];
    const float* fwx   = (const float*)d_in[3];
    const float* w1    = (const float*)d_in[4];
    const float* b1    = (const float*)d_in[5];
    const float* w2    = (const float*)d_in[6];
    const float* b2    = (const float*)d_in[7];
    const float* gamma = (const float*)d_in[8];
    const float* beta  = (const float*)d_in[9];
    float* out = (float*)d_out;

    cudaFuncSetAttribute(k_fwd_mma, cudaFuncAttributeMaxDynamicSharedMemorySize, FW_TOT);
    cudaFuncSetAttribute(k_mix_mma, cudaFuncAttributeMaxDynamicSharedMemorySize, MX_TOT);
    cudaFuncSetAttribute(k_inv_mma, cudaFuncAttributeMaxDynamicSharedMemorySize, IV_TOT);
    cudaFuncSetAttribute(k_mlp_mma, cudaFuncAttributeMaxDynamicSharedMemorySize, SM_MLP);

    k_weights<<<(BATCH*MODES*CI*CO)/256, 256>>>(att, fwy, fwx);
    k_wprep<<<128, 256>>>(w1, w2);
    k_tprep<<<256, 256>>>();
    k_fwd_mma<<<2*BATCH*MM, 256, FW_TOT>>>(x);
    k_mix_mma<<<2*BATCH*MODES, 256, MX_TOT>>>();
    k_inv_mma<<<2*BATCH*MM, 256, IV_TOT>>>();
    k_mlp_mma<<<(BATCH*MM*NN)/256, 256, SM_MLP>>>(b1, b2, gamma, beta, out);
}